// round 10
// baseline (speedup 1.0000x reference)
#include <cuda_runtime.h>
#include <cuda_bf16.h>
#include <math.h>
#include <stdint.h>

#define B_    64
#define FULLN 513
#define E_    768
#define NB    32
#define H_    12
#define HD    64
#define BH    (B_ * H_)       // 768
#define E4    (E_ / 4)        // 192
#define KE    2304            // extended K = 3 * 768

// -------- scratch (device globals; no allocation allowed) --------
__device__ float g_sampled[B_ * NB * E_];
__device__ float g_T[BH * E_];
__device__ float g_TK[BH * E_];
__device__ float g_partq[4 * B_ * E_];       // q split-K partials
__device__ float g_part[4 * B_ * E_];        // ctx / ao split-K partials

// bf16 extended operands.  A-mode segments: (hi, lo, hi); B-mode: (hi, hi, lo)
__device__ __nv_bfloat16 g_ext1[E_ * KE];    // T-ext, then US-ext (A-mode, reused)
__device__ __nv_bfloat16 g_Uext[E_ * KE];    // U-ext (A-mode)
__device__ __nv_bfloat16 g_Wsext[E_ * KE];   // Ws rows   (B-mode)
__device__ __nv_bfloat16 g_Wstext[E_ * KE];  // Ws^T rows (B-mode)
__device__ __nv_bfloat16 g_Wq[E_ * KE];      // Wq rows (B-mode)
__device__ __nv_bfloat16 g_Wv[E_ * KE];      // Wv rows (B-mode)
__device__ __nv_bfloat16 g_Wo[E_ * KE];      // Wo rows (B-mode)
__device__ __nv_bfloat16 g_bioext[B_ * KE];  // bio (A-mode)
__device__ __nv_bfloat16 g_ctxext[B_ * KE];  // ctx (A-mode)

// ================= helpers =================
__device__ __forceinline__ uint32_t smem_u32(const void* p) {
    uint32_t a;
    asm("{ .reg .u64 t; cvta.to.shared.u64 t, %1; cvt.u32.u64 %0, t; }" : "=r"(a) : "l"(p));
    return a;
}
__device__ __forceinline__ void ldsm_x4(uint32_t addr, uint32_t& r0, uint32_t& r1,
                                        uint32_t& r2, uint32_t& r3) {
    asm volatile("ldmatrix.sync.aligned.m8n8.x4.shared.b16 {%0,%1,%2,%3}, [%4];"
                 : "=r"(r0), "=r"(r1), "=r"(r2), "=r"(r3) : "r"(addr));
}
__device__ __forceinline__ void mma16816(float* d, const uint32_t* a, const uint32_t* b) {
    asm volatile("mma.sync.aligned.m16n8k16.row.col.f32.bf16.bf16.f32 "
                 "{%0,%1,%2,%3}, {%4,%5,%6,%7}, {%8,%9}, {%0,%1,%2,%3};"
                 : "+f"(d[0]), "+f"(d[1]), "+f"(d[2]), "+f"(d[3])
                 : "r"(a[0]), "r"(a[1]), "r"(a[2]), "r"(a[3]), "r"(b[0]), "r"(b[1]));
}
__device__ __forceinline__ void st_hilo_pair(__nv_bfloat16* base, float x, float y) {
    __nv_bfloat16 hx = __float2bfloat16(x), hy = __float2bfloat16(y);
    __nv_bfloat16 lx = __float2bfloat16(x - __bfloat162float(hx));
    __nv_bfloat16 ly = __float2bfloat16(y - __bfloat162float(hy));
    __nv_bfloat162 hp; hp.x = hx; hp.y = hy;
    __nv_bfloat162 lp; lp.x = lx; lp.y = ly;
    *(__nv_bfloat162*)(base) = hp;
    *(__nv_bfloat162*)(base + E_) = lp;
    *(__nv_bfloat162*)(base + 2 * E_) = hp;
}
#define CP16(saddr, gptr) \
    asm volatile("cp.async.ca.shared.global [%0], [%1], 16;" \
                 :: "r"(saddr), "l"(gptr))
#define CP_COMMIT() asm volatile("cp.async.commit_group;")
#define CP_WAIT(n)  asm volatile("cp.async.wait_group %0;" :: "n"(n))

// ================= HMMA GEMM: CH=64, cp.async, 6-stage pipeline ============
#define CH2   64
#define ROW2  144
#define TILE2 (64 * ROW2)
#define OPS2  (2 * TILE2)         // 18432
#define STG   6
#define SMEM2 (STG * OPS2)        // 110592

__global__ void __launch_bounds__(256) hmma_kernel(
    const __nv_bfloat16* __restrict__ Aext, long lda, long sAz,
    const __nv_bfloat16* __restrict__ Bext, long sBz,
    const float* __restrict__ bias,
    float* __restrict__ Cout, __nv_bfloat16* __restrict__ extOut,
    int nOffMul, int nSplit, int kLen, long splitStride)
{
    extern __shared__ __align__(16) char smem[];
    const int tid = threadIdx.x;
    const int w = tid >> 5, lane = tid & 31;
    const int m0 = blockIdx.y * 64;
    const int n0 = blockIdx.x * 64;
    const int zb = blockIdx.z / nSplit;
    const int sp = blockIdx.z - zb * nSplit;
    const int wm = w & 1, wn = w >> 1;
    const uint32_t sbase = smem_u32(smem);

    const int kcl  = kLen / nSplit;
    const int cnum = kcl / CH2;

    const int r  = tid >> 3;
    const int sg = tid & 7;
    const __nv_bfloat16* gA = Aext + zb * sAz + (long)(m0 + r) * lda + (long)sp * kcl + sg * 8;
    const __nv_bfloat16* gB = Bext + zb * sBz + (long)(n0 + r) * KE  + (long)sp * kcl + sg * 8;
    const uint32_t stA = (uint32_t)(r * ROW2 + sg * 16);
    const uint32_t stB = TILE2 + stA;
    const long gA32 = 32 * lda;
    const long gB32 = (long)32 * KE;

#define ISSUE(c) do { \
        uint32_t bb = sbase + ((c) % STG) * OPS2; \
        const __nv_bfloat16* pa = gA + (long)(c) * CH2; \
        const __nv_bfloat16* pb = gB + (long)(c) * CH2; \
        CP16(bb + stA,             pa); \
        CP16(bb + stA + 32 * ROW2, pa + gA32); \
        CP16(bb + stB,             pb); \
        CP16(bb + stB + 32 * ROW2, pb + gB32); \
        CP_COMMIT(); \
    } while (0)

    float acc[2][2][4];
#pragma unroll
    for (int i = 0; i < 2; i++)
#pragma unroll
        for (int j = 0; j < 2; j++)
#pragma unroll
            for (int v = 0; v < 4; v++) acc[i][j][v] = 0.f;

    // prologue: 5 chunks in flight
#pragma unroll
    for (int i = 0; i < STG - 1; i++)
        if (i < cnum) ISSUE(i);

    const int qq = lane >> 3, r8 = lane & 7;
    const uint32_t aoff = (uint32_t)((wm * 32 + (qq & 1) * 8 + r8) * ROW2 + ((qq >> 1) * 8) * 2);
    const uint32_t boff = (uint32_t)(TILE2 + (wn * 16 + (qq >> 1) * 8 + r8) * ROW2 + ((qq & 1) * 8) * 2);

    for (int c = 0; c < cnum; c++) {
        const int rem = cnum - 1 - c;       // chunks issued after c
        if (rem >= 4)      CP_WAIT(4);
        else if (rem == 3) CP_WAIT(3);
        else if (rem == 2) CP_WAIT(2);
        else if (rem == 1) CP_WAIT(1);
        else               CP_WAIT(0);
        __syncthreads();
        if (c + STG - 1 < cnum) ISSUE(c + STG - 1);
        const uint32_t base = sbase + (c % STG) * OPS2;
#pragma unroll
        for (int s = 0; s < 4; s++) {
            uint32_t af0[4], af1[4], bf[4];
            ldsm_x4(base + boff + s * 32, bf[0], bf[1], bf[2], bf[3]);
            ldsm_x4(base + aoff + s * 32, af0[0], af0[1], af0[2], af0[3]);
            ldsm_x4(base + aoff + 16 * ROW2 + s * 32, af1[0], af1[1], af1[2], af1[3]);
            mma16816(acc[0][0], af0, bf + 0);
            mma16816(acc[0][1], af0, bf + 2);
            mma16816(acc[1][0], af1, bf + 0);
            mma16816(acc[1][1], af1, bf + 2);
        }
    }
#undef ISSUE

    float* Cp = Cout ? (Cout + (long)sp * splitStride) : nullptr;
    const int col0 = n0 + zb * nOffMul;
    const int gr = lane >> 2, gc = (lane & 3) * 2;
#pragma unroll
    for (int mi = 0; mi < 2; mi++) {
#pragma unroll
        for (int ni = 0; ni < 2; ni++) {
            int rr = m0 + wm * 32 + mi * 16 + gr;
            int cc = col0 + wn * 16 + ni * 8 + gc;
            float bx = 0.f, by = 0.f;
            if (nSplit == 1 && bias) { bx = bias[cc]; by = bias[cc + 1]; }
            float x0 = acc[mi][ni][0] + bx, y0 = acc[mi][ni][1] + by;
            float x1 = acc[mi][ni][2] + bx, y1 = acc[mi][ni][3] + by;
            if (Cp) {
                *(float2*)(Cp + (long)rr * E_ + cc) = make_float2(x0, y0);
                *(float2*)(Cp + (long)(rr + 8) * E_ + cc) = make_float2(x1, y1);
            }
            if (nSplit == 1 && extOut) {
                st_hilo_pair(extOut + (long)rr * KE + cc, x0, y0);
                st_hilo_pair(extOut + (long)(rr + 8) * KE + cc, x1, y1);
            }
        }
    }
}

// ================= split-K reduce (ctx only) =================
__global__ void __launch_bounds__(256) reduce2_kernel(
    const float* __restrict__ part, const float* __restrict__ bias,
    float* __restrict__ Cout, __nv_bfloat16* __restrict__ extOut, int nSplit)
{
    const int total4 = B_ * E4;
    int i = blockIdx.x * blockDim.x + threadIdx.x;
    if (i >= total4) return;
    const float4* P = reinterpret_cast<const float4*>(part);
    float4 s = P[i];
    for (int sp = 1; sp < nSplit; sp++) {
        float4 v = P[(long)sp * total4 + i];
        s.x += v.x; s.y += v.y; s.z += v.z; s.w += v.w;
    }
    int rr = i / E4;
    int cc = (i - rr * E4) * 4;
    if (bias) {
        float4 b = *(const float4*)(bias + cc);
        s.x += b.x; s.y += b.y; s.z += b.z; s.w += b.w;
    }
    if (Cout) reinterpret_cast<float4*>(Cout)[i] = s;
    if (extOut) {
        __nv_bfloat16* e = extOut + (long)rr * KE + cc;
        st_hilo_pair(e, s.x, s.y);
        st_hilo_pair(e + 2, s.z, s.w);
    }
}

// ================= prep_all =================
__global__ void __launch_bounds__(256) prep_all_kernel(
    const float* __restrict__ Ws, const float* __restrict__ Win,
    const float* __restrict__ Wo, const float* __restrict__ bio,
    __nv_bfloat16* __restrict__ wsext, __nv_bfloat16* __restrict__ wstext,
    __nv_bfloat16* __restrict__ wq, __nv_bfloat16* __restrict__ wv,
    __nv_bfloat16* __restrict__ wox, __nv_bfloat16* __restrict__ bioext)
{
    __shared__ float tile[32][33];
    const int tx = threadIdx.x & 31, ty = threadIdx.x >> 5;
    const int bx = blockIdx.x * 32, by = blockIdx.y * 32;
    const int z = blockIdx.z;

    if (z == 0) {
#pragma unroll
        for (int j = 0; j < 4; j++) {
            float xv = Ws[(long)(by + ty + 8 * j) * E_ + bx + tx];
            tile[ty + 8 * j][tx] = xv;
            __nv_bfloat16 h = __float2bfloat16(xv);
            __nv_bfloat16 l = __float2bfloat16(xv - __bfloat162float(h));
            __nv_bfloat16* o = wsext + (long)(by + ty + 8 * j) * KE + bx + tx;
            o[0] = h; o[E_] = h; o[2 * E_] = l;
        }
        __syncthreads();
#pragma unroll
        for (int j = 0; j < 4; j++) {
            float xv = tile[tx][ty + 8 * j];
            __nv_bfloat16 h = __float2bfloat16(xv);
            __nv_bfloat16 l = __float2bfloat16(xv - __bfloat162float(h));
            __nv_bfloat16* o = wstext + (long)(bx + ty + 8 * j) * KE + by + tx;
            o[0] = h; o[E_] = h; o[2 * E_] = l;
        }
    } else if (z <= 3) {
        const float* s = (z == 1) ? Win : (z == 2) ? (Win + 2 * E_ * E_) : Wo;
        __nv_bfloat16* d = (z == 1) ? wq : (z == 2) ? wv : wox;
#pragma unroll
        for (int j = 0; j < 4; j++) {
            int rr = by + ty + 8 * j;
            float xv = s[(long)rr * E_ + bx + tx];
            __nv_bfloat16 h = __float2bfloat16(xv);
            __nv_bfloat16 l = __float2bfloat16(xv - __bfloat162float(h));
            __nv_bfloat16* o = d + (long)rr * KE + bx + tx;
            o[0] = h; o[E_] = h; o[2 * E_] = l;
        }
    } else {
        if (by >= B_) return;
#pragma unroll
        for (int j = 0; j < 4; j++) {
            int rr = by + ty + 8 * j;
            if (rr >= B_) continue;
            float xv = bio[(long)rr * E_ + bx + tx];
            __nv_bfloat16 h = __float2bfloat16(xv);
            __nv_bfloat16 l = __float2bfloat16(xv - __bfloat162float(h));
            __nv_bfloat16* o = bioext + (long)rr * KE + bx + tx;
            o[0] = h; o[E_] = l; o[2 * E_] = h;
        }
    }
}

// ================= trilinear sample =================
__global__ void __launch_bounds__(192) sample_kernel(
    const float* __restrict__ x, const float* __restrict__ base,
    const float* __restrict__ off, float* __restrict__ out)
{
    int bp = blockIdx.x;
    int b = bp >> 5, p = bp & 31;

    float cx = fminf(fmaxf(base[p * 3 + 0] + off[bp * 3 + 0], -1.f), 1.f);
    float cy = fminf(fmaxf(base[p * 3 + 1] + off[bp * 3 + 1], -1.f), 1.f);
    float cz = fminf(fmaxf(base[p * 3 + 2] + off[bp * 3 + 2], -1.f), 1.f);

    float ix = (cx + 1.f) * 3.5f;
    float iy = (cy + 1.f) * 3.5f;
    float iz = (cz + 1.f) * 3.5f;
    float fx = floorf(ix), fy = floorf(iy), fz = floorf(iz);
    float wx = ix - fx, wy = iy - fy, wz = iz - fz;
    int x0 = max(0, min(7, (int)fx));
    int y0 = max(0, min(7, (int)fy));
    int z0 = max(0, min(7, (int)fz));
    int x1 = min(7, x0 + 1), y1 = min(7, y0 + 1), z1 = min(7, z0 + 1);

    int r000 = 1 + ((z0 * 8 + y0) * 8 + x0);
    int r001 = 1 + ((z0 * 8 + y0) * 8 + x1);
    int r010 = 1 + ((z0 * 8 + y1) * 8 + x0);
    int r011 = 1 + ((z0 * 8 + y1) * 8 + x1);
    int r100 = 1 + ((z1 * 8 + y0) * 8 + x0);
    int r101 = 1 + ((z1 * 8 + y0) * 8 + x1);
    int r110 = 1 + ((z1 * 8 + y1) * 8 + x0);
    int r111 = 1 + ((z1 * 8 + y1) * 8 + x1);

    float w000 = (1.f - wz) * (1.f - wy) * (1.f - wx);
    float w001 = (1.f - wz) * (1.f - wy) * wx;
    float w010 = (1.f - wz) * wy * (1.f - wx);
    float w011 = (1.f - wz) * wy * wx;
    float w100 = wz * (1.f - wy) * (1.f - wx);
    float w101 = wz * (1.f - wy) * wx;
    float w110 = wz * wy * (1.f - wx);
    float w111 = wz * wy * wx;

    const float4* X = reinterpret_cast<const float4*>(x) + (long)b * FULLN * E4;
    int t = threadIdx.x;
    float4 s = make_float4(0.f, 0.f, 0.f, 0.f);
#define ACC(R, W) { float4 v = X[(R) * E4 + t]; \
        s.x = fmaf(W, v.x, s.x); s.y = fmaf(W, v.y, s.y); \
        s.z = fmaf(W, v.z, s.z); s.w = fmaf(W, v.w, s.w); }
    ACC(r000, w000) ACC(r001, w001) ACC(r010, w010) ACC(r011, w011)
    ACC(r100, w100) ACC(r101, w101) ACC(r110, w110) ACC(r111, w111)
#undef ACC
    reinterpret_cast<float4*>(out)[(long)bp * E4 + t] = s;
}

// ===== T_h = q_h @ Wk_h (K=64), q from 4-way partials + bq; ext epilogue ====
__global__ void __launch_bounds__(256) qk_head_kernel(
    const float* __restrict__ partq, const float* __restrict__ bin,
    const float* __restrict__ Wk,
    float* __restrict__ T, __nv_bfloat16* __restrict__ Text)
{
    __shared__ __align__(16) float As[64][68];
    __shared__ __align__(16) float Bs[64][68];
    const int tid = threadIdx.x;
    const int n0 = blockIdx.x * 64;
    const int h = blockIdx.y;
    const long spl = (long)B_ * E_;

    const int r = tid >> 2, cbase = (tid & 3) * 16;
#pragma unroll
    for (int j = 0; j < 4; j++) {
        int c4 = cbase + j * 4;
        long qo = (long)r * E_ + h * HD + c4;
        float4 a = *(const float4*)(partq + qo);
#pragma unroll
        for (int sp = 1; sp < 4; sp++) {
            float4 v = *(const float4*)(partq + sp * spl + qo);
            a.x += v.x; a.y += v.y; a.z += v.z; a.w += v.w;
        }
        float4 bq = *(const float4*)(bin + h * HD + c4);
        a.x += bq.x; a.y += bq.y; a.z += bq.z; a.w += bq.w;
        As[c4 + 0][r] = a.x; As[c4 + 1][r] = a.y;
        As[c4 + 2][r] = a.z; As[c4 + 3][r] = a.w;
        float4 b = *(const float4*)(Wk + (long)(h * HD + r) * E_ + n0 + c4);
        *(float4*)(&Bs[r][c4]) = b;
    }
    __syncthreads();

    const int ty = tid >> 4, tx = tid & 15;
    float acc[4][4];
#pragma unroll
    for (int i = 0; i < 4; i++)
#pragma unroll
        for (int j = 0; j < 4; j++) acc[i][j] = 0.f;

#pragma unroll 8
    for (int k = 0; k < 64; k++) {
        float4 av = *(const float4*)(&As[k][ty * 4]);
        float4 bv = *(const float4*)(&Bs[k][tx * 4]);
        float a[4] = {av.x, av.y, av.z, av.w};
        float b[4] = {bv.x, bv.y, bv.z, bv.w};
#pragma unroll
        for (int i = 0; i < 4; i++)
#pragma unroll
            for (int j = 0; j < 4; j++)
                acc[i][j] = fmaf(a[i], b[j], acc[i][j]);
    }

#pragma unroll
    for (int i = 0; i < 4; i++) {
        int b = ty * 4 + i;
        long bh = (long)b * H_ + h;
#pragma unroll
        for (int j = 0; j < 4; j += 2) {
            int n = n0 + tx * 4 + j;
            float x0 = acc[i][j], x1 = acc[i][j + 1];
            *(float2*)(T + bh * E_ + n) = make_float2(x0, x1);
            st_hilo_pair(Text + bh * KE + n, x0, x1);
        }
    }
}

// ====== fused per-batch scores + softmax + US-ext ==========================
// grid = B_, 256 threads. smem: tk[12][768] + samp[32][768] + sc[12][32] + cb[12]
#define SC_SMEM ((H_ * E_ + NB * E_ + H_ * NB + H_ + 4) * 4)

__global__ void __launch_bounds__(256) scores_us_kernel(
    const float* __restrict__ TK, const float* __restrict__ T,
    const float* __restrict__ partq, const float* __restrict__ sampled,
    const float* __restrict__ in_proj_b, const float* __restrict__ bs,
    __nv_bfloat16* __restrict__ ext)
{
    extern __shared__ __align__(16) float sm[];
    float* tk   = sm;                       // 9216
    float* samp = tk + H_ * E_;             // 24576
    float* sc   = samp + NB * E_;           // 384
    float* cb   = sc + H_ * NB;             // 12

    const int b = blockIdx.x;
    const int tid = threadIdx.x;
    const int w = tid >> 5, lane = tid & 31;
    const long spl = (long)B_ * E_;

    // ---- load TK rows (12 x 768, contiguous) and sampled[b] (32 x 768) ----
    {
        const float4* src = (const float4*)(TK + (long)b * H_ * E_);
        float4* dst = (float4*)tk;
        for (int i = tid; i < H_ * E4; i += 256) dst[i] = src[i];
        const float4* s2 = (const float4*)(sampled + (long)b * NB * E_);
        float4* d2 = (float4*)samp;
        for (int i = tid; i < NB * E4; i += 256) d2[i] = s2[i];
    }
    // ---- cb[h] = T[bh]·bs + q_h·bk_h  (warp w: h = w, and w+8 if w<4) ----
#pragma unroll
    for (int hh = 0; hh < 2; hh++) {
        int h = (hh == 0) ? w : (w + 8);
        if (hh == 1 && w >= 4) break;
        long bh = (long)b * H_ + h;
        float s = 0.f;
        const float* Trow = T + bh * E_;
        for (int i = 0; i < 24; i++) {
            int f = lane + 32 * i;
            s += Trow[f] * bs[f];
        }
#pragma unroll
        for (int e2 = 0; e2 < 2; e2++) {
            int k = lane + 32 * e2;
            long qo = (long)b * E_ + h * HD + k;
            float qv = partq[qo] + partq[spl + qo] + partq[2 * spl + qo] + partq[3 * spl + qo]
                     + in_proj_b[h * HD + k];
            s += qv * in_proj_b[E_ + h * HD + k];
        }
#pragma unroll
        for (int o = 16; o; o >>= 1) s += __shfl_xor_sync(0xffffffffu, s, o);
        if (lane == 0) cb[h] = s;
    }
    __syncthreads();

    // ---- scores: 384 (h,p) dots of length 768 from smem ----
    for (int j = 0; j < 48; j++) {
        int pair = w * 48 + j;
        int h = pair >> 5, p = pair & 31;
        const float* tkr = tk + h * E_;
        const float* sr  = samp + p * E_;
        float d = 0.f;
        for (int i = 0; i < 24; i++) {
            int f = lane + 32 * i;
            d = fmaf(tkr[f], sr[f], d);
        }
#pragma unroll
        for (int o = 16; o; o >>= 1) d += __shfl_xor_sync(0xffffffffu, d, o);
        if (lane == 0) sc[h * NB + p] = (d + cb[h]) * 0.125f;
    }
    __syncthreads();

    // ---- softmax per head (warp w: h = w, and w+8 if w<4) ----
#pragma unroll
    for (int hh = 0; hh < 2; hh++) {
        int h = (hh == 0) ? w : (w + 8);
        if (hh == 1 && w >= 4) break;
        float s = sc[h * NB + lane];
        float m = s;
#pragma unroll
        for (int o = 16; o; o >>= 1) m = fmaxf(m, __shfl_xor_sync(0xffffffffu, m, o));
        float e = expf(s - m);
        float sum = e;
#pragma unroll
        for (int o = 16; o; o >>= 1) sum += __shfl_xor_sync(0xffffffffu, sum, o);
        sc[h * NB + lane] = e / sum;
    }
    __syncthreads();

    // ---- US: 12 x 192 float4 outputs; 9 per thread ----
    const float4* samp4 = (const float4*)samp;
#pragma unroll
    for (int i = 0; i < 9; i++) {
        int idx = tid + 256 * i;           // 0 .. 2303
        int h = idx / E4;
        int f4 = idx - h * E4;
        const float* scr = sc + h * NB;
        float4 acc = make_float4(0.f, 0.f, 0.f, 0.f);
#pragma unroll 8
        for (int p = 0; p < NB; p++) {
            float wv = scr[p];
            float4 v = samp4[p * E4 + f4];
            acc.x = fmaf(wv, v.x, acc.x); acc.y = fmaf(wv, v.y, acc.y);
            acc.z = fmaf(wv, v.z, acc.z); acc.w = fmaf(wv, v.w, acc.w);
        }
        long bh = (long)b * H_ + h;
        __nv_bfloat16* e = ext + bh * KE + 4 * f4;
        st_hilo_pair(e, acc.x, acc.y);
        st_hilo_pair(e + 2, acc.z, acc.w);
    }
}

// ====== broadcast out: fused ao split-K reduce + bias + confidence =========
#define ONS 16
__global__ void __launch_bounds__(192) out_kernel(
    const float* __restrict__ part, const float* __restrict__ bo,
    const float* __restrict__ conf, float4* __restrict__ out)
{
    const int b = blockIdx.y, t = threadIdx.x;
    const long spl = (long)B_ * E_;
    long o = (long)b * E_ + 4 * t;
    float4 s = *(const float4*)(part + o);
#pragma unroll
    for (int sp = 1; sp < 4; sp++) {
        float4 v = *(const float4*)(part + sp * spl + o);
        s.x += v.x; s.y += v.y; s.z += v.z; s.w += v.w;
    }
    float4 bb = *(const float4*)(bo + 4 * t);
    float cf = conf[b];
    s.x = (s.x + bb.x) * cf; s.y = (s.y + bb.y) * cf;
    s.z = (s.z + bb.z) * cf; s.w = (s.w + bb.w) * cf;

    const int nlo = blockIdx.x * 33;
    const int nhi = min(nlo + 33, FULLN);
    float4* dst = out + (long)b * FULLN * E4 + t;
    for (int n = nlo; n < nhi; n++)
        dst[(long)n * E4] = s;
}

// ================================================================
extern "C" void kernel_launch(void* const* d_in, const int* in_sizes, int n_in,
                              void* d_out, int out_size)
{
    const float* x    = (const float*)d_in[0];
    const float* bio  = (const float*)d_in[1];
    const float* base = (const float*)d_in[2];
    const float* off  = (const float*)d_in[3];
    const float* conf = (const float*)d_in[4];
    const float* Ws   = (const float*)d_in[5];
    const float* bs   = (const float*)d_in[6];
    const float* Win  = (const float*)d_in[7];
    const float* bin  = (const float*)d_in[8];
    const float* Wo   = (const float*)d_in[9];
    const float* bo   = (const float*)d_in[10];
    float* out = (float*)d_out;

    float *sampled, *T, *TK, *part, *partq;
    cudaGetSymbolAddress((void**)&sampled, g_sampled);
    cudaGetSymbolAddress((void**)&T,     g_T);
    cudaGetSymbolAddress((void**)&TK,    g_TK);
    cudaGetSymbolAddress((void**)&part,  g_part);
    cudaGetSymbolAddress((void**)&partq, g_partq);

    __nv_bfloat16 *ext1, *Uext, *Wsext, *Wstext, *Wq, *Wv, *Wox, *bioext, *ctxext;
    cudaGetSymbolAddress((void**)&ext1,   g_ext1);
    cudaGetSymbolAddress((void**)&Uext,   g_Uext);
    cudaGetSymbolAddress((void**)&Wsext,  g_Wsext);
    cudaGetSymbolAddress((void**)&Wstext, g_Wstext);
    cudaGetSymbolAddress((void**)&Wq,     g_Wq);
    cudaGetSymbolAddress((void**)&Wv,     g_Wv);
    cudaGetSymbolAddress((void**)&Wox,    g_Wo);
    cudaGetSymbolAddress((void**)&bioext, g_bioext);
    cudaGetSymbolAddress((void**)&ctxext, g_ctxext);

    cudaFuncSetAttribute(hmma_kernel,
                         cudaFuncAttributeMaxDynamicSharedMemorySize, SMEM2);
    cudaFuncSetAttribute(scores_us_kernel,
                         cudaFuncAttributeMaxDynamicSharedMemorySize, SC_SMEM);

    const long spl = (long)B_ * E_;

    // 1) trilinear sample
    sample_kernel<<<B_ * NB, 192>>>(x, base, off, sampled);

    // 2) all conversions, one launch
    prep_all_kernel<<<dim3(24, 24, 5), 256>>>(
        Ws, Win, Wo, bio, Wsext, Wstext, Wq, Wv, Wox, bioext);

    // 3) q partials = bio @ Wq.T  (split-K=4; reduce fused into consumers)
    hmma_kernel<<<dim3(12, 1, 4), 256, SMEM2>>>(
        bioext, KE, 0, Wq, 0, nullptr, partq, nullptr, 0, 4, KE, spl);

    // 4) T_h = q_h @ Wk_h  (q reduced inline) -> T fp32 + T ext
    qk_head_kernel<<<dim3(12, H_), 256>>>(partq, bin, Win + E_ * E_, T, ext1);

    // 5) TK = T @ Ws  (big HMMA)
    hmma_kernel<<<dim3(12, 12, 1), 256, SMEM2>>>(
        ext1, KE, 0, Wstext, 0, nullptr, TK, nullptr, 0, 1, KE, 0);

    // 6) scores + softmax + US-ext (fused, per-batch)
    scores_us_kernel<<<B_, 256, SC_SMEM>>>(TK, T, partq, sampled, bin, bs, ext1);

    // 7) U = US @ Ws.T + bs  (big HMMA) -> U ext
    hmma_kernel<<<dim3(12, 12, 1), 256, SMEM2>>>(
        ext1, KE, 0, Wsext, 0, bs, nullptr, Uext, 0, 1, KE, 0);

    // 8) ctx_h = U_h @ Wv_h.T  (per-head, split-K=4) + reduce -> ctx ext
    hmma_kernel<<<dim3(1, 1, H_ * 4), 256, SMEM2>>>(
        Uext, (long)H_ * KE, KE, Wv, (long)HD * KE,
        nullptr, part, nullptr, HD, 4, KE, spl);
    reduce2_kernel<<<48, 256>>>(part, bin + 2 * E_, nullptr, ctxext, 4);

    // 9) ao partials = ctx @ Wo.T  (split-K=4; reduce fused into out)
    hmma_kernel<<<dim3(12, 1, 4), 256, SMEM2>>>(
        ctxext, KE, 0, Wox, 0, nullptr, part, nullptr, 0, 4, KE, spl);

    // 10) out = (reduce(ao) + bo) * confidence, broadcast over N
    out_kernel<<<dim3(ONS, B_), 192>>>(part, bo, conf, (float4*)out);
}

// round 11
// speedup vs baseline: 1.0931x; 1.0931x over previous
#include <cuda_runtime.h>
#include <cuda_bf16.h>
#include <math.h>
#include <stdint.h>

#define B_    64
#define FULLN 513
#define E_    768
#define NB    32
#define H_    12
#define HD    64
#define BH    (B_ * H_)       // 768
#define E4    (E_ / 4)        // 192
#define KE    2304            // extended K = 3 * 768

// -------- scratch (device globals; no allocation allowed) --------
__device__ float g_sampled[B_ * NB * E_];
__device__ float g_T[BH * E_];
__device__ float g_partq[4 * B_ * E_];       // q split-K partials
__device__ float g_part[4 * B_ * E_];        // ctx / ao split-K partials
__device__ float g_partBig[2 * BH * E_];     // TK / U split-K partials (4.7 MB)

// bf16 extended operands.  A-mode segments: (hi, lo, hi); B-mode: (hi, hi, lo)
__device__ __nv_bfloat16 g_ext1[E_ * KE];    // T-ext, then US-ext (A-mode, reused)
__device__ __nv_bfloat16 g_Uext[E_ * KE];    // U-ext (A-mode)
__device__ __nv_bfloat16 g_Wsext[E_ * KE];   // Ws rows   (B-mode)
__device__ __nv_bfloat16 g_Wstext[E_ * KE];  // Ws^T rows (B-mode)
__device__ __nv_bfloat16 g_Wq[E_ * KE];      // Wq rows (B-mode)
__device__ __nv_bfloat16 g_Wv[E_ * KE];      // Wv rows (B-mode)
__device__ __nv_bfloat16 g_Wo[E_ * KE];      // Wo rows (B-mode)
__device__ __nv_bfloat16 g_bioext[B_ * KE];  // bio (A-mode)
__device__ __nv_bfloat16 g_ctxext[B_ * KE];  // ctx (A-mode)

// ================= helpers =================
__device__ __forceinline__ uint32_t smem_u32(const void* p) {
    uint32_t a;
    asm("{ .reg .u64 t; cvta.to.shared.u64 t, %1; cvt.u32.u64 %0, t; }" : "=r"(a) : "l"(p));
    return a;
}
__device__ __forceinline__ void ldsm_x4(uint32_t addr, uint32_t& r0, uint32_t& r1,
                                        uint32_t& r2, uint32_t& r3) {
    asm volatile("ldmatrix.sync.aligned.m8n8.x4.shared.b16 {%0,%1,%2,%3}, [%4];"
                 : "=r"(r0), "=r"(r1), "=r"(r2), "=r"(r3) : "r"(addr));
}
__device__ __forceinline__ void mma16816(float* d, const uint32_t* a, const uint32_t* b) {
    asm volatile("mma.sync.aligned.m16n8k16.row.col.f32.bf16.bf16.f32 "
                 "{%0,%1,%2,%3}, {%4,%5,%6,%7}, {%8,%9}, {%0,%1,%2,%3};"
                 : "+f"(d[0]), "+f"(d[1]), "+f"(d[2]), "+f"(d[3])
                 : "r"(a[0]), "r"(a[1]), "r"(a[2]), "r"(a[3]), "r"(b[0]), "r"(b[1]));
}
__device__ __forceinline__ void st_hilo_pair(__nv_bfloat16* base, float x, float y) {
    __nv_bfloat16 hx = __float2bfloat16(x), hy = __float2bfloat16(y);
    __nv_bfloat16 lx = __float2bfloat16(x - __bfloat162float(hx));
    __nv_bfloat16 ly = __float2bfloat16(y - __bfloat162float(hy));
    __nv_bfloat162 hp; hp.x = hx; hp.y = hy;
    __nv_bfloat162 lp; lp.x = lx; lp.y = ly;
    *(__nv_bfloat162*)(base) = hp;
    *(__nv_bfloat162*)(base + E_) = lp;
    *(__nv_bfloat162*)(base + 2 * E_) = hp;
}
#define CP16(saddr, gptr) \
    asm volatile("cp.async.ca.shared.global [%0], [%1], 16;" \
                 :: "r"(saddr), "l"(gptr))
#define CP_COMMIT() asm volatile("cp.async.commit_group;")
#define CP_WAIT(n)  asm volatile("cp.async.wait_group %0;" :: "n"(n))

// ================= HMMA GEMM: CH=64, cp.async, 6-stage pipeline ============
#define CH2   64
#define ROW2  144
#define TILE2 (64 * ROW2)
#define OPS2  (2 * TILE2)         // 18432
#define STG   6
#define SMEM2 (STG * OPS2)        // 110592

__global__ void __launch_bounds__(256) hmma_kernel(
    const __nv_bfloat16* __restrict__ Aext, long lda, long sAz,
    const __nv_bfloat16* __restrict__ Bext, long sBz,
    const float* __restrict__ bias,
    float* __restrict__ Cout, __nv_bfloat16* __restrict__ extOut,
    int nOffMul, int nSplit, int kLen, long splitStride)
{
    extern __shared__ __align__(16) char smem[];
    const int tid = threadIdx.x;
    const int w = tid >> 5, lane = tid & 31;
    const int m0 = blockIdx.y * 64;
    const int n0 = blockIdx.x * 64;
    const int zb = blockIdx.z / nSplit;
    const int sp = blockIdx.z - zb * nSplit;
    const int wm = w & 1, wn = w >> 1;
    const uint32_t sbase = smem_u32(smem);

    const int kcl  = kLen / nSplit;
    const int cnum = kcl / CH2;

    const int r  = tid >> 3;
    const int sg = tid & 7;
    const __nv_bfloat16* gA = Aext + zb * sAz + (long)(m0 + r) * lda + (long)sp * kcl + sg * 8;
    const __nv_bfloat16* gB = Bext + zb * sBz + (long)(n0 + r) * KE  + (long)sp * kcl + sg * 8;
    const uint32_t stA = (uint32_t)(r * ROW2 + sg * 16);
    const uint32_t stB = TILE2 + stA;
    const long gA32 = 32 * lda;
    const long gB32 = (long)32 * KE;

#define ISSUE(c) do { \
        uint32_t bb = sbase + ((c) % STG) * OPS2; \
        const __nv_bfloat16* pa = gA + (long)(c) * CH2; \
        const __nv_bfloat16* pb = gB + (long)(c) * CH2; \
        CP16(bb + stA,             pa); \
        CP16(bb + stA + 32 * ROW2, pa + gA32); \
        CP16(bb + stB,             pb); \
        CP16(bb + stB + 32 * ROW2, pb + gB32); \
        CP_COMMIT(); \
    } while (0)

    float acc[2][2][4];
#pragma unroll
    for (int i = 0; i < 2; i++)
#pragma unroll
        for (int j = 0; j < 2; j++)
#pragma unroll
            for (int v = 0; v < 4; v++) acc[i][j][v] = 0.f;

    // prologue: up to 5 chunks in flight
#pragma unroll
    for (int i = 0; i < STG - 1; i++)
        if (i < cnum) ISSUE(i);

    const int qq = lane >> 3, r8 = lane & 7;
    const uint32_t aoff = (uint32_t)((wm * 32 + (qq & 1) * 8 + r8) * ROW2 + ((qq >> 1) * 8) * 2);
    const uint32_t boff = (uint32_t)(TILE2 + (wn * 16 + (qq >> 1) * 8 + r8) * ROW2 + ((qq & 1) * 8) * 2);

    for (int c = 0; c < cnum; c++) {
        const int rem = cnum - 1 - c;
        if (rem >= 4)      CP_WAIT(4);
        else if (rem == 3) CP_WAIT(3);
        else if (rem == 2) CP_WAIT(2);
        else if (rem == 1) CP_WAIT(1);
        else               CP_WAIT(0);
        __syncthreads();
        if (c + STG - 1 < cnum) ISSUE(c + STG - 1);
        const uint32_t base = sbase + (c % STG) * OPS2;
#pragma unroll
        for (int s = 0; s < 4; s++) {
            uint32_t af0[4], af1[4], bf[4];
            ldsm_x4(base + boff + s * 32, bf[0], bf[1], bf[2], bf[3]);
            ldsm_x4(base + aoff + s * 32, af0[0], af0[1], af0[2], af0[3]);
            ldsm_x4(base + aoff + 16 * ROW2 + s * 32, af1[0], af1[1], af1[2], af1[3]);
            mma16816(acc[0][0], af0, bf + 0);
            mma16816(acc[0][1], af0, bf + 2);
            mma16816(acc[1][0], af1, bf + 0);
            mma16816(acc[1][1], af1, bf + 2);
        }
    }
#undef ISSUE

    float* Cp = Cout ? (Cout + (long)sp * splitStride) : nullptr;
    const int col0 = n0 + zb * nOffMul;
    const int gr = lane >> 2, gc = (lane & 3) * 2;
#pragma unroll
    for (int mi = 0; mi < 2; mi++) {
#pragma unroll
        for (int ni = 0; ni < 2; ni++) {
            int rr = m0 + wm * 32 + mi * 16 + gr;
            int cc = col0 + wn * 16 + ni * 8 + gc;
            float bx = 0.f, by = 0.f;
            if (nSplit == 1 && bias) { bx = bias[cc]; by = bias[cc + 1]; }
            float x0 = acc[mi][ni][0] + bx, y0 = acc[mi][ni][1] + by;
            float x1 = acc[mi][ni][2] + bx, y1 = acc[mi][ni][3] + by;
            if (Cp) {
                *(float2*)(Cp + (long)rr * E_ + cc) = make_float2(x0, y0);
                *(float2*)(Cp + (long)(rr + 8) * E_ + cc) = make_float2(x1, y1);
            }
            if (nSplit == 1 && extOut) {
                st_hilo_pair(extOut + (long)rr * KE + cc, x0, y0);
                st_hilo_pair(extOut + (long)(rr + 8) * KE + cc, x1, y1);
            }
        }
    }
}

// ================= split-K reduce (parameterized rows) =================
__global__ void __launch_bounds__(256) reduce2_kernel(
    const float* __restrict__ part, const float* __restrict__ bias,
    float* __restrict__ Cout, __nv_bfloat16* __restrict__ extOut,
    int nSplit, int total4)
{
    int i = blockIdx.x * blockDim.x + threadIdx.x;
    if (i >= total4) return;
    const float4* P = reinterpret_cast<const float4*>(part);
    float4 s = P[i];
    for (int sp = 1; sp < nSplit; sp++) {
        float4 v = P[(long)sp * total4 + i];
        s.x += v.x; s.y += v.y; s.z += v.z; s.w += v.w;
    }
    int rr = i / E4;
    int cc = (i - rr * E4) * 4;
    if (bias) {
        float4 b = *(const float4*)(bias + cc);
        s.x += b.x; s.y += b.y; s.z += b.z; s.w += b.w;
    }
    if (Cout) reinterpret_cast<float4*>(Cout)[i] = s;
    if (extOut) {
        __nv_bfloat16* e = extOut + (long)rr * KE + cc;
        st_hilo_pair(e, s.x, s.y);
        st_hilo_pair(e + 2, s.z, s.w);
    }
}

// ================= prep_all =================
__global__ void __launch_bounds__(256) prep_all_kernel(
    const float* __restrict__ Ws, const float* __restrict__ Win,
    const float* __restrict__ Wo, const float* __restrict__ bio,
    __nv_bfloat16* __restrict__ wsext, __nv_bfloat16* __restrict__ wstext,
    __nv_bfloat16* __restrict__ wq, __nv_bfloat16* __restrict__ wv,
    __nv_bfloat16* __restrict__ wox, __nv_bfloat16* __restrict__ bioext)
{
    __shared__ float tile[32][33];
    const int tx = threadIdx.x & 31, ty = threadIdx.x >> 5;
    const int bx = blockIdx.x * 32, by = blockIdx.y * 32;
    const int z = blockIdx.z;

    if (z == 0) {
#pragma unroll
        for (int j = 0; j < 4; j++) {
            float xv = Ws[(long)(by + ty + 8 * j) * E_ + bx + tx];
            tile[ty + 8 * j][tx] = xv;
            __nv_bfloat16 h = __float2bfloat16(xv);
            __nv_bfloat16 l = __float2bfloat16(xv - __bfloat162float(h));
            __nv_bfloat16* o = wsext + (long)(by + ty + 8 * j) * KE + bx + tx;
            o[0] = h; o[E_] = h; o[2 * E_] = l;
        }
        __syncthreads();
#pragma unroll
        for (int j = 0; j < 4; j++) {
            float xv = tile[tx][ty + 8 * j];
            __nv_bfloat16 h = __float2bfloat16(xv);
            __nv_bfloat16 l = __float2bfloat16(xv - __bfloat162float(h));
            __nv_bfloat16* o = wstext + (long)(bx + ty + 8 * j) * KE + by + tx;
            o[0] = h; o[E_] = h; o[2 * E_] = l;
        }
    } else if (z <= 3) {
        const float* s = (z == 1) ? Win : (z == 2) ? (Win + 2 * E_ * E_) : Wo;
        __nv_bfloat16* d = (z == 1) ? wq : (z == 2) ? wv : wox;
#pragma unroll
        for (int j = 0; j < 4; j++) {
            int rr = by + ty + 8 * j;
            float xv = s[(long)rr * E_ + bx + tx];
            __nv_bfloat16 h = __float2bfloat16(xv);
            __nv_bfloat16 l = __float2bfloat16(xv - __bfloat162float(h));
            __nv_bfloat16* o = d + (long)rr * KE + bx + tx;
            o[0] = h; o[E_] = h; o[2 * E_] = l;
        }
    } else {
        if (by >= B_) return;
#pragma unroll
        for (int j = 0; j < 4; j++) {
            int rr = by + ty + 8 * j;
            if (rr >= B_) continue;
            float xv = bio[(long)rr * E_ + bx + tx];
            __nv_bfloat16 h = __float2bfloat16(xv);
            __nv_bfloat16 l = __float2bfloat16(xv - __bfloat162float(h));
            __nv_bfloat16* o = bioext + (long)rr * KE + bx + tx;
            o[0] = h; o[E_] = l; o[2 * E_] = h;
        }
    }
}

// ================= trilinear sample =================
__global__ void __launch_bounds__(192) sample_kernel(
    const float* __restrict__ x, const float* __restrict__ base,
    const float* __restrict__ off, float* __restrict__ out)
{
    int bp = blockIdx.x;
    int b = bp >> 5, p = bp & 31;

    float cx = fminf(fmaxf(base[p * 3 + 0] + off[bp * 3 + 0], -1.f), 1.f);
    float cy = fminf(fmaxf(base[p * 3 + 1] + off[bp * 3 + 1], -1.f), 1.f);
    float cz = fminf(fmaxf(base[p * 3 + 2] + off[bp * 3 + 2], -1.f), 1.f);

    float ix = (cx + 1.f) * 3.5f;
    float iy = (cy + 1.f) * 3.5f;
    float iz = (cz + 1.f) * 3.5f;
    float fx = floorf(ix), fy = floorf(iy), fz = floorf(iz);
    float wx = ix - fx, wy = iy - fy, wz = iz - fz;
    int x0 = max(0, min(7, (int)fx));
    int y0 = max(0, min(7, (int)fy));
    int z0 = max(0, min(7, (int)fz));
    int x1 = min(7, x0 + 1), y1 = min(7, y0 + 1), z1 = min(7, z0 + 1);

    int r000 = 1 + ((z0 * 8 + y0) * 8 + x0);
    int r001 = 1 + ((z0 * 8 + y0) * 8 + x1);
    int r010 = 1 + ((z0 * 8 + y1) * 8 + x0);
    int r011 = 1 + ((z0 * 8 + y1) * 8 + x1);
    int r100 = 1 + ((z1 * 8 + y0) * 8 + x0);
    int r101 = 1 + ((z1 * 8 + y0) * 8 + x1);
    int r110 = 1 + ((z1 * 8 + y1) * 8 + x0);
    int r111 = 1 + ((z1 * 8 + y1) * 8 + x1);

    float w000 = (1.f - wz) * (1.f - wy) * (1.f - wx);
    float w001 = (1.f - wz) * (1.f - wy) * wx;
    float w010 = (1.f - wz) * wy * (1.f - wx);
    float w011 = (1.f - wz) * wy * wx;
    float w100 = wz * (1.f - wy) * (1.f - wx);
    float w101 = wz * (1.f - wy) * wx;
    float w110 = wz * wy * (1.f - wx);
    float w111 = wz * wy * wx;

    const float4* X = reinterpret_cast<const float4*>(x) + (long)b * FULLN * E4;
    int t = threadIdx.x;
    float4 s = make_float4(0.f, 0.f, 0.f, 0.f);
#define ACC(R, W) { float4 v = X[(R) * E4 + t]; \
        s.x = fmaf(W, v.x, s.x); s.y = fmaf(W, v.y, s.y); \
        s.z = fmaf(W, v.z, s.z); s.w = fmaf(W, v.w, s.w); }
    ACC(r000, w000) ACC(r001, w001) ACC(r010, w010) ACC(r011, w011)
    ACC(r100, w100) ACC(r101, w101) ACC(r110, w110) ACC(r111, w111)
#undef ACC
    reinterpret_cast<float4*>(out)[(long)bp * E4 + t] = s;
}

// ===== T_h = q_h @ Wk_h (K=64), q from 4-way partials + bq; ext epilogue ====
__global__ void __launch_bounds__(256) qk_head_kernel(
    const float* __restrict__ partq, const float* __restrict__ bin,
    const float* __restrict__ Wk,
    float* __restrict__ T, __nv_bfloat16* __restrict__ Text)
{
    __shared__ __align__(16) float As[64][68];
    __shared__ __align__(16) float Bs[64][68];
    const int tid = threadIdx.x;
    const int n0 = blockIdx.x * 64;
    const int h = blockIdx.y;
    const long spl = (long)B_ * E_;

    const int r = tid >> 2, cbase = (tid & 3) * 16;
#pragma unroll
    for (int j = 0; j < 4; j++) {
        int c4 = cbase + j * 4;
        long qo = (long)r * E_ + h * HD + c4;
        float4 a = *(const float4*)(partq + qo);
#pragma unroll
        for (int sp = 1; sp < 4; sp++) {
            float4 v = *(const float4*)(partq + sp * spl + qo);
            a.x += v.x; a.y += v.y; a.z += v.z; a.w += v.w;
        }
        float4 bq = *(const float4*)(bin + h * HD + c4);
        a.x += bq.x; a.y += bq.y; a.z += bq.z; a.w += bq.w;
        As[c4 + 0][r] = a.x; As[c4 + 1][r] = a.y;
        As[c4 + 2][r] = a.z; As[c4 + 3][r] = a.w;
        float4 b = *(const float4*)(Wk + (long)(h * HD + r) * E_ + n0 + c4);
        *(float4*)(&Bs[r][c4]) = b;
    }
    __syncthreads();

    const int ty = tid >> 4, tx = tid & 15;
    float acc[4][4];
#pragma unroll
    for (int i = 0; i < 4; i++)
#pragma unroll
        for (int j = 0; j < 4; j++) acc[i][j] = 0.f;

#pragma unroll 8
    for (int k = 0; k < 64; k++) {
        float4 av = *(const float4*)(&As[k][ty * 4]);
        float4 bv = *(const float4*)(&Bs[k][tx * 4]);
        float a[4] = {av.x, av.y, av.z, av.w};
        float b[4] = {bv.x, bv.y, bv.z, bv.w};
#pragma unroll
        for (int i = 0; i < 4; i++)
#pragma unroll
            for (int j = 0; j < 4; j++)
                acc[i][j] = fmaf(a[i], b[j], acc[i][j]);
    }

#pragma unroll
    for (int i = 0; i < 4; i++) {
        int b = ty * 4 + i;
        long bh = (long)b * H_ + h;
#pragma unroll
        for (int j = 0; j < 4; j += 2) {
            int n = n0 + tx * 4 + j;
            float x0 = acc[i][j], x1 = acc[i][j + 1];
            *(float2*)(T + bh * E_ + n) = make_float2(x0, x1);
            st_hilo_pair(Text + bh * KE + n, x0, x1);
        }
    }
}

// ====== fused scores + softmax + US-ext (per-bh; TK from 2 partials) =======
__global__ void __launch_bounds__(128) scores_us_kernel(
    const float* __restrict__ partTK, const float* __restrict__ T,
    const float* __restrict__ partq, const float* __restrict__ sampled,
    const float* __restrict__ in_proj_b, const float* __restrict__ bs,
    __nv_bfloat16* __restrict__ ext)
{
    int bh = blockIdx.x;
    int b = bh / H_, h = bh % H_;
    __shared__ float tk[E_];
    __shared__ float sc[NB];
    __shared__ float red[4];
    __shared__ float cbs;
    int tid = threadIdx.x;
    int w = tid >> 5, lane = tid & 31;
    const long spl = (long)B_ * E_;
    const long splTK = (long)BH * E_;

    const float* TKrow  = partTK + (long)bh * E_;
    const float* TKrow2 = partTK + splTK + (long)bh * E_;
    const float* Trow   = T + (long)bh * E_;
    float part = 0.f;
    for (int f = tid; f < E_; f += 128) {
        float t = TKrow[f] + TKrow2[f];
        tk[f] = t;
        part += Trow[f] * bs[f];
    }
    if (tid < HD) {
        long qo = (long)b * E_ + h * HD + tid;
        float qv = partq[qo] + partq[spl + qo] + partq[2 * spl + qo] + partq[3 * spl + qo]
                 + in_proj_b[h * HD + tid];
        part += qv * in_proj_b[E_ + h * HD + tid];
    }
#pragma unroll
    for (int o = 16; o; o >>= 1) part += __shfl_xor_sync(0xffffffffu, part, o);
    if (lane == 0) red[w] = part;
    __syncthreads();
    if (tid == 0) cbs = red[0] + red[1] + red[2] + red[3];
    __syncthreads();

    float cb = cbs;
#pragma unroll
    for (int pi = 0; pi < 8; pi++) {
        int p = w * 8 + pi;
        const float* srow = sampled + ((long)b * NB + p) * E_;
        float d = 0.f;
        for (int f = lane; f < E_; f += 32) d = fmaf(tk[f], srow[f], d);
#pragma unroll
        for (int o = 16; o; o >>= 1) d += __shfl_xor_sync(0xffffffffu, d, o);
        if (lane == 0) sc[p] = (d + cb) * 0.125f;
    }
    __syncthreads();
    if (tid < NB) {
        float s = sc[tid];
        float m = s;
#pragma unroll
        for (int o = 16; o; o >>= 1) m = fmaxf(m, __shfl_xor_sync(0xffffffffu, m, o));
        float e = expf(s - m);
        float sum = e;
#pragma unroll
        for (int o = 16; o; o >>= 1) sum += __shfl_xor_sync(0xffffffffu, sum, o);
        sc[tid] = e / sum;
    }
    __syncthreads();

    const float4* S = reinterpret_cast<const float4*>(sampled) + (long)b * NB * E4;
    for (int f = tid; f < E4; f += 128) {
        float4 acc = make_float4(0.f, 0.f, 0.f, 0.f);
#pragma unroll 8
        for (int p = 0; p < NB; p++) {
            float wv = sc[p];
            float4 s = S[p * E4 + f];
            acc.x = fmaf(wv, s.x, acc.x); acc.y = fmaf(wv, s.y, acc.y);
            acc.z = fmaf(wv, s.z, acc.z); acc.w = fmaf(wv, s.w, acc.w);
        }
        __nv_bfloat16* e = ext + (long)bh * KE + 4 * f;
        st_hilo_pair(e, acc.x, acc.y);
        st_hilo_pair(e + 2, acc.z, acc.w);
    }
}

// ====== broadcast out: fused ao split-K reduce + bias + confidence =========
#define ONS 16
__global__ void __launch_bounds__(192) out_kernel(
    const float* __restrict__ part, const float* __restrict__ bo,
    const float* __restrict__ conf, float4* __restrict__ out)
{
    const int b = blockIdx.y, t = threadIdx.x;
    const long spl = (long)B_ * E_;
    long o = (long)b * E_ + 4 * t;
    float4 s = *(const float4*)(part + o);
#pragma unroll
    for (int sp = 1; sp < 4; sp++) {
        float4 v = *(const float4*)(part + sp * spl + o);
        s.x += v.x; s.y += v.y; s.z += v.z; s.w += v.w;
    }
    float4 bb = *(const float4*)(bo + 4 * t);
    float cf = conf[b];
    s.x = (s.x + bb.x) * cf; s.y = (s.y + bb.y) * cf;
    s.z = (s.z + bb.z) * cf; s.w = (s.w + bb.w) * cf;

    const int nlo = blockIdx.x * 33;
    const int nhi = min(nlo + 33, FULLN);
    float4* dst = out + (long)b * FULLN * E4 + t;
    for (int n = nlo; n < nhi; n++)
        dst[(long)n * E4] = s;
}

// ================================================================
extern "C" void kernel_launch(void* const* d_in, const int* in_sizes, int n_in,
                              void* d_out, int out_size)
{
    const float* x    = (const float*)d_in[0];
    const float* bio  = (const float*)d_in[1];
    const float* base = (const float*)d_in[2];
    const float* off  = (const float*)d_in[3];
    const float* conf = (const float*)d_in[4];
    const float* Ws   = (const float*)d_in[5];
    const float* bs   = (const float*)d_in[6];
    const float* Win  = (const float*)d_in[7];
    const float* bin  = (const float*)d_in[8];
    const float* Wo   = (const float*)d_in[9];
    const float* bo   = (const float*)d_in[10];
    float* out = (float*)d_out;

    float *sampled, *T, *part, *partq, *partBig;
    cudaGetSymbolAddress((void**)&sampled, g_sampled);
    cudaGetSymbolAddress((void**)&T,       g_T);
    cudaGetSymbolAddress((void**)&part,    g_part);
    cudaGetSymbolAddress((void**)&partq,   g_partq);
    cudaGetSymbolAddress((void**)&partBig, g_partBig);

    __nv_bfloat16 *ext1, *Uext, *Wsext, *Wstext, *Wq, *Wv, *Wox, *bioext, *ctxext;
    cudaGetSymbolAddress((void**)&ext1,   g_ext1);
    cudaGetSymbolAddress((void**)&Uext,   g_Uext);
    cudaGetSymbolAddress((void**)&Wsext,  g_Wsext);
    cudaGetSymbolAddress((void**)&Wstext, g_Wstext);
    cudaGetSymbolAddress((void**)&Wq,     g_Wq);
    cudaGetSymbolAddress((void**)&Wv,     g_Wv);
    cudaGetSymbolAddress((void**)&Wox,    g_Wo);
    cudaGetSymbolAddress((void**)&bioext, g_bioext);
    cudaGetSymbolAddress((void**)&ctxext, g_ctxext);

    cudaFuncSetAttribute(hmma_kernel,
                         cudaFuncAttributeMaxDynamicSharedMemorySize, SMEM2);

    const long spl    = (long)B_ * E_;
    const long splBig = (long)BH * E_;

    // 1) trilinear sample
    sample_kernel<<<B_ * NB, 192>>>(x, base, off, sampled);

    // 2) all conversions, one launch
    prep_all_kernel<<<dim3(24, 24, 5), 256>>>(
        Ws, Win, Wo, bio, Wsext, Wstext, Wq, Wv, Wox, bioext);

    // 3) q partials = bio @ Wq.T  (split-K=4; reduce fused into consumers)
    hmma_kernel<<<dim3(12, 1, 4), 256, SMEM2>>>(
        bioext, KE, 0, Wq, 0, nullptr, partq, nullptr, 0, 4, KE, spl);

    // 4) T_h = q_h @ Wk_h  (q reduced inline) -> T fp32 + T ext
    qk_head_kernel<<<dim3(12, H_), 256>>>(partq, bin, Win + E_ * E_, T, ext1);

    // 5) TK partials = T @ Ws  (split-K=2; reduce fused into scores_us)
    hmma_kernel<<<dim3(12, 12, 2), 256, SMEM2>>>(
        ext1, KE, 0, Wstext, 0, nullptr, partBig, nullptr, 0, 2, KE, splBig);

    // 6) scores + softmax + US-ext (fused, per-bh; sums TK partials inline)
    scores_us_kernel<<<BH, 128>>>(partBig, T, partq, sampled, bin, bs, ext1);

    // 7) U partials = US @ Ws.T  (split-K=2) + reduce(+bs) -> U ext
    hmma_kernel<<<dim3(12, 12, 2), 256, SMEM2>>>(
        ext1, KE, 0, Wsext, 0, nullptr, partBig, nullptr, 0, 2, KE, splBig);
    reduce2_kernel<<<(BH * E4 + 255) / 256, 256>>>(
        partBig, bs, nullptr, Uext, 2, BH * E4);

    // 8) ctx_h = U_h @ Wv_h.T  (per-head, split-K=4) + reduce -> ctx ext
    hmma_kernel<<<dim3(1, 1, H_ * 4), 256, SMEM2>>>(
        Uext, (long)H_ * KE, KE, Wv, (long)HD * KE,
        nullptr, part, nullptr, HD, 4, KE, spl);
    reduce2_kernel<<<48, 256>>>(part, bin + 2 * E_, nullptr, ctxext, 4, B_ * E4);

    // 9) ao partials = ctx @ Wo.T  (split-K=4; reduce fused into out)
    hmma_kernel<<<dim3(12, 1, 4), 256, SMEM2>>>(
        ctxext, KE, 0, Wox, 0, nullptr, part, nullptr, 0, 4, KE, spl);

    // 10) out = (reduce(ao) + bo) * confidence, broadcast over N
    out_kernel<<<dim3(ONS, B_), 192>>>(part, bo, conf, (float4*)out);
}

// round 14
// speedup vs baseline: 1.1125x; 1.0178x over previous
#include <cuda_runtime.h>
#include <cuda_bf16.h>
#include <math.h>
#include <stdint.h>

#define B_    64
#define FULLN 513
#define E_    768
#define NB    32
#define H_    12
#define HD    64
#define BH    (B_ * H_)       // 768
#define E4    (E_ / 4)        // 192
#define KE    2304            // extended K = 3 * 768

// -------- scratch (device globals; no allocation allowed) --------
__device__ float g_sampled[B_ * NB * E_];
__device__ float g_T[BH * E_];
__device__ float g_TK[BH * E_];
__device__ float g_partq[4 * B_ * E_];       // q split-K partials
__device__ float g_part[4 * B_ * E_];        // ctx / ao split-K partials

// bf16 extended operands.  A-mode segments: (hi, lo, hi); B-mode: (hi, hi, lo)
__device__ __nv_bfloat16 g_ext1[E_ * KE];    // T-ext, then US-ext (A-mode, reused)
__device__ __nv_bfloat16 g_Uext[E_ * KE];    // U-ext (A-mode)
__device__ __nv_bfloat16 g_Wsext[E_ * KE];   // Ws rows   (B-mode)
__device__ __nv_bfloat16 g_Wstext[E_ * KE];  // Ws^T rows (B-mode)
__device__ __nv_bfloat16 g_Wq[E_ * KE];      // Wq rows (B-mode)
__device__ __nv_bfloat16 g_Wv[E_ * KE];      // Wv rows (B-mode)
__device__ __nv_bfloat16 g_Wo[E_ * KE];      // Wo rows (B-mode)
__device__ __nv_bfloat16 g_bioext[B_ * KE];  // bio (A-mode)
__device__ __nv_bfloat16 g_ctxext[B_ * KE];  // ctx (A-mode)

// ================= helpers =================
__device__ __forceinline__ uint32_t smem_u32(const void* p) {
    uint32_t a;
    asm("{ .reg .u64 t; cvta.to.shared.u64 t, %1; cvt.u32.u64 %0, t; }" : "=r"(a) : "l"(p));
    return a;
}
__device__ __forceinline__ void ldsm_x4(uint32_t addr, uint32_t& r0, uint32_t& r1,
                                        uint32_t& r2, uint32_t& r3) {
    asm volatile("ldmatrix.sync.aligned.m8n8.x4.shared.b16 {%0,%1,%2,%3}, [%4];"
                 : "=r"(r0), "=r"(r1), "=r"(r2), "=r"(r3) : "r"(addr));
}
__device__ __forceinline__ void mma16816(float* d, const uint32_t* a, const uint32_t* b) {
    asm volatile("mma.sync.aligned.m16n8k16.row.col.f32.bf16.bf16.f32 "
                 "{%0,%1,%2,%3}, {%4,%5,%6,%7}, {%8,%9}, {%0,%1,%2,%3};"
                 : "+f"(d[0]), "+f"(d[1]), "+f"(d[2]), "+f"(d[3])
                 : "r"(a[0]), "r"(a[1]), "r"(a[2]), "r"(a[3]), "r"(b[0]), "r"(b[1]));
}
__device__ __forceinline__ void st_hilo_pair(__nv_bfloat16* base, float x, float y) {
    __nv_bfloat16 hx = __float2bfloat16(x), hy = __float2bfloat16(y);
    __nv_bfloat16 lx = __float2bfloat16(x - __bfloat162float(hx));
    __nv_bfloat16 ly = __float2bfloat16(y - __bfloat162float(hy));
    __nv_bfloat162 hp; hp.x = hx; hp.y = hy;
    __nv_bfloat162 lp; lp.x = lx; lp.y = ly;
    *(__nv_bfloat162*)(base) = hp;
    *(__nv_bfloat162*)(base + E_) = lp;
    *(__nv_bfloat162*)(base + 2 * E_) = hp;
}
#define CP16(saddr, gptr) \
    asm volatile("cp.async.ca.shared.global [%0], [%1], 16;" \
                 :: "r"(saddr), "l"(gptr))
#define CP_COMMIT() asm volatile("cp.async.commit_group;")
#define CP_WAIT1()  asm volatile("cp.async.wait_group 1;")
#define CP_WAIT0()  asm volatile("cp.async.wait_group 0;")

// ================= HMMA GEMM: CH=64, cp.async, 3-buffer pipeline ===========
#define CH2   64
#define ROW2  144
#define TILE2 (64 * ROW2)
#define OPS2  (2 * TILE2)
#define SMEM2 (3 * OPS2)          // 55296

__global__ void __launch_bounds__(256) hmma_kernel(
    const __nv_bfloat16* __restrict__ Aext, long lda, long sAz,
    const __nv_bfloat16* __restrict__ Bext, long sBz,
    const float* __restrict__ bias,
    float* __restrict__ Cout, __nv_bfloat16* __restrict__ extOut,
    int nOffMul, int nSplit, int kLen, long splitStride)
{
    extern __shared__ __align__(16) char smem[];
    const int tid = threadIdx.x;
    const int w = tid >> 5, lane = tid & 31;
    const int m0 = blockIdx.y * 64;
    const int n0 = blockIdx.x * 64;
    const int zb = blockIdx.z / nSplit;
    const int sp = blockIdx.z - zb * nSplit;
    const int wm = w & 1, wn = w >> 1;
    const uint32_t sbase = smem_u32(smem);

    const int kcl  = kLen / nSplit;
    const int cnum = kcl / CH2;

    const int r  = tid >> 3;
    const int sg = tid & 7;
    const __nv_bfloat16* gA = Aext + zb * sAz + (long)(m0 + r) * lda + (long)sp * kcl + sg * 8;
    const __nv_bfloat16* gB = Bext + zb * sBz + (long)(n0 + r) * KE  + (long)sp * kcl + sg * 8;
    const uint32_t stA = (uint32_t)(r * ROW2 + sg * 16);
    const uint32_t stB = TILE2 + stA;
    const long gA32 = 32 * lda;
    const long gB32 = (long)32 * KE;

#define ISSUE(c) do { \
        uint32_t bb = sbase + ((c) % 3) * OPS2; \
        const __nv_bfloat16* pa = gA + (long)(c) * CH2; \
        const __nv_bfloat16* pb = gB + (long)(c) * CH2; \
        CP16(bb + stA,             pa); \
        CP16(bb + stA + 32 * ROW2, pa + gA32); \
        CP16(bb + stB,             pb); \
        CP16(bb + stB + 32 * ROW2, pb + gB32); \
        CP_COMMIT(); \
    } while (0)

    float acc[2][2][4];
#pragma unroll
    for (int i = 0; i < 2; i++)
#pragma unroll
        for (int j = 0; j < 2; j++)
#pragma unroll
            for (int v = 0; v < 4; v++) acc[i][j][v] = 0.f;

    ISSUE(0);
    ISSUE(1);

    const int qq = lane >> 3, r8 = lane & 7;
    const uint32_t aoff = (uint32_t)((wm * 32 + (qq & 1) * 8 + r8) * ROW2 + ((qq >> 1) * 8) * 2);
    const uint32_t boff = (uint32_t)(TILE2 + (wn * 16 + (qq >> 1) * 8 + r8) * ROW2 + ((qq & 1) * 8) * 2);

    for (int c = 0; c < cnum; c++) {
        if (c + 1 < cnum) CP_WAIT1(); else CP_WAIT0();
        __syncthreads();
        if (c + 2 < cnum) ISSUE(c + 2);
        const uint32_t base = sbase + (c % 3) * OPS2;
#pragma unroll
        for (int s = 0; s < 4; s++) {
            uint32_t af0[4], af1[4], bf[4];
            ldsm_x4(base + boff + s * 32, bf[0], bf[1], bf[2], bf[3]);
            ldsm_x4(base + aoff + s * 32, af0[0], af0[1], af0[2], af0[3]);
            ldsm_x4(base + aoff + 16 * ROW2 + s * 32, af1[0], af1[1], af1[2], af1[3]);
            mma16816(acc[0][0], af0, bf + 0);
            mma16816(acc[0][1], af0, bf + 2);
            mma16816(acc[1][0], af1, bf + 0);
            mma16816(acc[1][1], af1, bf + 2);
        }
    }
#undef ISSUE

    float* Cp = Cout ? (Cout + (long)sp * splitStride) : nullptr;
    const int col0 = n0 + zb * nOffMul;
    const int gr = lane >> 2, gc = (lane & 3) * 2;
#pragma unroll
    for (int mi = 0; mi < 2; mi++) {
#pragma unroll
        for (int ni = 0; ni < 2; ni++) {
            int rr = m0 + wm * 32 + mi * 16 + gr;
            int cc = col0 + wn * 16 + ni * 8 + gc;
            float bx = 0.f, by = 0.f;
            if (nSplit == 1 && bias) { bx = bias[cc]; by = bias[cc + 1]; }
            float x0 = acc[mi][ni][0] + bx, y0 = acc[mi][ni][1] + by;
            float x1 = acc[mi][ni][2] + bx, y1 = acc[mi][ni][3] + by;
            if (Cp) {
                *(float2*)(Cp + (long)rr * E_ + cc) = make_float2(x0, y0);
                *(float2*)(Cp + (long)(rr + 8) * E_ + cc) = make_float2(x1, y1);
            }
            if (nSplit == 1 && extOut) {
                st_hilo_pair(extOut + (long)rr * KE + cc, x0, y0);
                st_hilo_pair(extOut + (long)(rr + 8) * KE + cc, x1, y1);
            }
        }
    }
}

// ================= split-K reduce (ctx only) =================
__global__ void __launch_bounds__(256) reduce2_kernel(
    const float* __restrict__ part, const float* __restrict__ bias,
    float* __restrict__ Cout, __nv_bfloat16* __restrict__ extOut, int nSplit)
{
    const int total4 = B_ * E4;
    int i = blockIdx.x * blockDim.x + threadIdx.x;
    if (i >= total4) return;
    const float4* P = reinterpret_cast<const float4*>(part);
    float4 s = P[i];
    for (int sp = 1; sp < nSplit; sp++) {
        float4 v = P[(long)sp * total4 + i];
        s.x += v.x; s.y += v.y; s.z += v.z; s.w += v.w;
    }
    int rr = i / E4;
    int cc = (i - rr * E4) * 4;
    if (bias) {
        float4 b = *(const float4*)(bias + cc);
        s.x += b.x; s.y += b.y; s.z += b.z; s.w += b.w;
    }
    if (Cout) reinterpret_cast<float4*>(Cout)[i] = s;
    if (extOut) {
        __nv_bfloat16* e = extOut + (long)rr * KE + cc;
        st_hilo_pair(e, s.x, s.y);
        st_hilo_pair(e + 2, s.z, s.w);
    }
}

// ================= prep_all =================
__global__ void __launch_bounds__(256) prep_all_kernel(
    const float* __restrict__ Ws, const float* __restrict__ Win,
    const float* __restrict__ Wo, const float* __restrict__ bio,
    __nv_bfloat16* __restrict__ wsext, __nv_bfloat16* __restrict__ wstext,
    __nv_bfloat16* __restrict__ wq, __nv_bfloat16* __restrict__ wv,
    __nv_bfloat16* __restrict__ wox, __nv_bfloat16* __restrict__ bioext)
{
    __shared__ float tile[32][33];
    const int tx = threadIdx.x & 31, ty = threadIdx.x >> 5;
    const int bx = blockIdx.x * 32, by = blockIdx.y * 32;
    const int z = blockIdx.z;

    if (z == 0) {
#pragma unroll
        for (int j = 0; j < 4; j++) {
            float xv = Ws[(long)(by + ty + 8 * j) * E_ + bx + tx];
            tile[ty + 8 * j][tx] = xv;
            __nv_bfloat16 h = __float2bfloat16(xv);
            __nv_bfloat16 l = __float2bfloat16(xv - __bfloat162float(h));
            __nv_bfloat16* o = wsext + (long)(by + ty + 8 * j) * KE + bx + tx;
            o[0] = h; o[E_] = h; o[2 * E_] = l;
        }
        __syncthreads();
#pragma unroll
        for (int j = 0; j < 4; j++) {
            float xv = tile[tx][ty + 8 * j];
            __nv_bfloat16 h = __float2bfloat16(xv);
            __nv_bfloat16 l = __float2bfloat16(xv - __bfloat162float(h));
            __nv_bfloat16* o = wstext + (long)(bx + ty + 8 * j) * KE + by + tx;
            o[0] = h; o[E_] = h; o[2 * E_] = l;
        }
    } else if (z <= 3) {
        const float* s = (z == 1) ? Win : (z == 2) ? (Win + 2 * E_ * E_) : Wo;
        __nv_bfloat16* d = (z == 1) ? wq : (z == 2) ? wv : wox;
#pragma unroll
        for (int j = 0; j < 4; j++) {
            int rr = by + ty + 8 * j;
            float xv = s[(long)rr * E_ + bx + tx];
            __nv_bfloat16 h = __float2bfloat16(xv);
            __nv_bfloat16 l = __float2bfloat16(xv - __bfloat162float(h));
            __nv_bfloat16* o = d + (long)rr * KE + bx + tx;
            o[0] = h; o[E_] = h; o[2 * E_] = l;
        }
    } else {
        if (by >= B_) return;
#pragma unroll
        for (int j = 0; j < 4; j++) {
            int rr = by + ty + 8 * j;
            if (rr >= B_) continue;
            float xv = bio[(long)rr * E_ + bx + tx];
            __nv_bfloat16 h = __float2bfloat16(xv);
            __nv_bfloat16 l = __float2bfloat16(xv - __bfloat162float(h));
            __nv_bfloat16* o = bioext + (long)rr * KE + bx + tx;
            o[0] = h; o[E_] = l; o[2 * E_] = h;
        }
    }
}

// ================= trilinear sample =================
__global__ void __launch_bounds__(192) sample_kernel(
    const float* __restrict__ x, const float* __restrict__ base,
    const float* __restrict__ off, float* __restrict__ out)
{
    int bp = blockIdx.x;
    int b = bp >> 5, p = bp & 31;

    float cx = fminf(fmaxf(base[p * 3 + 0] + off[bp * 3 + 0], -1.f), 1.f);
    float cy = fminf(fmaxf(base[p * 3 + 1] + off[bp * 3 + 1], -1.f), 1.f);
    float cz = fminf(fmaxf(base[p * 3 + 2] + off[bp * 3 + 2], -1.f), 1.f);

    float ix = (cx + 1.f) * 3.5f;
    float iy = (cy + 1.f) * 3.5f;
    float iz = (cz + 1.f) * 3.5f;
    float fx = floorf(ix), fy = floorf(iy), fz = floorf(iz);
    float wx = ix - fx, wy = iy - fy, wz = iz - fz;
    int x0 = max(0, min(7, (int)fx));
    int y0 = max(0, min(7, (int)fy));
    int z0 = max(0, min(7, (int)fz));
    int x1 = min(7, x0 + 1), y1 = min(7, y0 + 1), z1 = min(7, z0 + 1);

    int r000 = 1 + ((z0 * 8 + y0) * 8 + x0);
    int r001 = 1 + ((z0 * 8 + y0) * 8 + x1);
    int r010 = 1 + ((z0 * 8 + y1) * 8 + x0);
    int r011 = 1 + ((z0 * 8 + y1) * 8 + x1);
    int r100 = 1 + ((z1 * 8 + y0) * 8 + x0);
    int r101 = 1 + ((z1 * 8 + y0) * 8 + x1);
    int r110 = 1 + ((z1 * 8 + y1) * 8 + x0);
    int r111 = 1 + ((z1 * 8 + y1) * 8 + x1);

    float w000 = (1.f - wz) * (1.f - wy) * (1.f - wx);
    float w001 = (1.f - wz) * (1.f - wy) * wx;
    float w010 = (1.f - wz) * wy * (1.f - wx);
    float w011 = (1.f - wz) * wy * wx;
    float w100 = wz * (1.f - wy) * (1.f - wx);
    float w101 = wz * (1.f - wy) * wx;
    float w110 = wz * wy * (1.f - wx);
    float w111 = wz * wy * wx;

    const float4* X = reinterpret_cast<const float4*>(x) + (long)b * FULLN * E4;
    int t = threadIdx.x;
    float4 s = make_float4(0.f, 0.f, 0.f, 0.f);
#define ACC(R, W) { float4 v = X[(R) * E4 + t]; \
        s.x = fmaf(W, v.x, s.x); s.y = fmaf(W, v.y, s.y); \
        s.z = fmaf(W, v.z, s.z); s.w = fmaf(W, v.w, s.w); }
    ACC(r000, w000) ACC(r001, w001) ACC(r010, w010) ACC(r011, w011)
    ACC(r100, w100) ACC(r101, w101) ACC(r110, w110) ACC(r111, w111)
#undef ACC
    reinterpret_cast<float4*>(out)[(long)bp * E4 + t] = s;
}

// ===== T_h = q_h @ Wk_h (K=64), N-tile 32, grid (24, 12) =====
// q built inline from 4-way partials + bq; ext epilogue. 288 CTAs (~2/SM).
__global__ void __launch_bounds__(256) qk_head_kernel(
    const float* __restrict__ partq, const float* __restrict__ bin,
    const float* __restrict__ Wk,
    float* __restrict__ T, __nv_bfloat16* __restrict__ Text)
{
    __shared__ __align__(16) float As[64][68];   // As[k][b]
    __shared__ __align__(16) float Bs[64][36];   // Bs[k][n] (32 + pad)
    const int tid = threadIdx.x;
    const int n0 = blockIdx.x * 32;
    const int h = blockIdx.y;
    const long spl = (long)B_ * E_;

    const int r = tid >> 2;             // 0..63
    // ---- A: q rows (64 b) x 64 k, reduced from partials, stored transposed
    const int cb4 = (tid & 3) * 16;
#pragma unroll
    for (int j = 0; j < 4; j++) {
        int c4 = cb4 + j * 4;
        long qo = (long)r * E_ + h * HD + c4;
        float4 a = *(const float4*)(partq + qo);
#pragma unroll
        for (int sp = 1; sp < 4; sp++) {
            float4 v = *(const float4*)(partq + sp * spl + qo);
            a.x += v.x; a.y += v.y; a.z += v.z; a.w += v.w;
        }
        float4 bq = *(const float4*)(bin + h * HD + c4);
        a.x += bq.x; a.y += bq.y; a.z += bq.z; a.w += bq.w;
        As[c4 + 0][r] = a.x; As[c4 + 1][r] = a.y;
        As[c4 + 2][r] = a.z; As[c4 + 3][r] = a.w;
    }
    // ---- B: Wk rows (64 k) x 32 n: each thread 8 floats of one row
    {
        int seg = (tid & 3) * 8;
        const float* wr = Wk + (long)(h * HD + r) * E_ + n0 + seg;
        float4 b0 = *(const float4*)wr;
        float4 b1 = *(const float4*)(wr + 4);
        *(float4*)(&Bs[r][seg]) = b0;
        *(float4*)(&Bs[r][seg + 4]) = b1;
    }
    __syncthreads();

    const int ty = tid >> 4, tx = tid & 15;   // 16 x 16: 4 rows x 2 cols each
    float acc[4][2];
#pragma unroll
    for (int i = 0; i < 4; i++) { acc[i][0] = 0.f; acc[i][1] = 0.f; }

#pragma unroll 8
    for (int k = 0; k < 64; k++) {
        float4 av = *(const float4*)(&As[k][ty * 4]);
        float2 bv = *(const float2*)(&Bs[k][tx * 2]);
        float a[4] = {av.x, av.y, av.z, av.w};
#pragma unroll
        for (int i = 0; i < 4; i++) {
            acc[i][0] = fmaf(a[i], bv.x, acc[i][0]);
            acc[i][1] = fmaf(a[i], bv.y, acc[i][1]);
        }
    }

#pragma unroll
    for (int i = 0; i < 4; i++) {
        int b = ty * 4 + i;
        long bh = (long)b * H_ + h;
        int n = n0 + tx * 2;
        float x0 = acc[i][0], x1 = acc[i][1];
        *(float2*)(T + bh * E_ + n) = make_float2(x0, x1);
        st_hilo_pair(Text + bh * KE + n, x0, x1);
    }
}

// ====== fused scores + softmax + US-ext (per-bh) ===========================
__global__ void __launch_bounds__(128) scores_us_kernel(
    const float* __restrict__ TK, const float* __restrict__ T,
    const float* __restrict__ partq, const float* __restrict__ sampled,
    const float* __restrict__ in_proj_b, const float* __restrict__ bs,
    __nv_bfloat16* __restrict__ ext)
{
    int bh = blockIdx.x;
    int b = bh / H_, h = bh % H_;
    __shared__ float tk[E_];
    __shared__ float sc[NB];
    __shared__ float red[4];
    __shared__ float cbs;
    int tid = threadIdx.x;
    int w = tid >> 5, lane = tid & 31;
    const long spl = (long)B_ * E_;

    const float* TKrow = TK + (long)bh * E_;
    const float* Trow  = T + (long)bh * E_;
    float part = 0.f;
    for (int f = tid; f < E_; f += 128) {
        float t = TKrow[f];
        tk[f] = t;
        part += Trow[f] * bs[f];
    }
    if (tid < HD) {
        long qo = (long)b * E_ + h * HD + tid;
        float qv = partq[qo] + partq[spl + qo] + partq[2 * spl + qo] + partq[3 * spl + qo]
                 + in_proj_b[h * HD + tid];
        part += qv * in_proj_b[E_ + h * HD + tid];
    }
#pragma unroll
    for (int o = 16; o; o >>= 1) part += __shfl_xor_sync(0xffffffffu, part, o);
    if (lane == 0) red[w] = part;
    __syncthreads();
    if (tid == 0) cbs = red[0] + red[1] + red[2] + red[3];
    __syncthreads();

    float cb = cbs;
#pragma unroll
    for (int pi = 0; pi < 8; pi++) {
        int p = w * 8 + pi;
        const float* srow = sampled + ((long)b * NB + p) * E_;
        float d = 0.f;
        for (int f = lane; f < E_; f += 32) d = fmaf(tk[f], srow[f], d);
#pragma unroll
        for (int o = 16; o; o >>= 1) d += __shfl_xor_sync(0xffffffffu, d, o);
        if (lane == 0) sc[p] = (d + cb) * 0.125f;
    }
    __syncthreads();
    if (tid < NB) {
        float s = sc[tid];
        float m = s;
#pragma unroll
        for (int o = 16; o; o >>= 1) m = fmaxf(m, __shfl_xor_sync(0xffffffffu, m, o));
        float e = expf(s - m);
        float sum = e;
#pragma unroll
        for (int o = 16; o; o >>= 1) sum += __shfl_xor_sync(0xffffffffu, sum, o);
        sc[tid] = e / sum;
    }
    __syncthreads();

    const float4* S = reinterpret_cast<const float4*>(sampled) + (long)b * NB * E4;
    for (int f = tid; f < E4; f += 128) {
        float4 acc = make_float4(0.f, 0.f, 0.f, 0.f);
#pragma unroll 8
        for (int p = 0; p < NB; p++) {
            float wv = sc[p];
            float4 s = S[p * E4 + f];
            acc.x = fmaf(wv, s.x, acc.x); acc.y = fmaf(wv, s.y, acc.y);
            acc.z = fmaf(wv, s.z, acc.z); acc.w = fmaf(wv, s.w, acc.w);
        }
        __nv_bfloat16* e = ext + (long)bh * KE + 4 * f;
        st_hilo_pair(e, acc.x, acc.y);
        st_hilo_pair(e + 2, acc.z, acc.w);
    }
}

// ====== broadcast out: fused ao split-K reduce + bias + confidence =========
#define ONS 16
__global__ void __launch_bounds__(192) out_kernel(
    const float* __restrict__ part, const float* __restrict__ bo,
    const float* __restrict__ conf, float4* __restrict__ out)
{
    const int b = blockIdx.y, t = threadIdx.x;
    const long spl = (long)B_ * E_;
    long o = (long)b * E_ + 4 * t;
    float4 s = *(const float4*)(part + o);
#pragma unroll
    for (int sp = 1; sp < 4; sp++) {
        float4 v = *(const float4*)(part + sp * spl + o);
        s.x += v.x; s.y += v.y; s.z += v.z; s.w += v.w;
    }
    float4 bb = *(const float4*)(bo + 4 * t);
    float cf = conf[b];
    s.x = (s.x + bb.x) * cf; s.y = (s.y + bb.y) * cf;
    s.z = (s.z + bb.z) * cf; s.w = (s.w + bb.w) * cf;

    const int nlo = blockIdx.x * 33;
    const int nhi = min(nlo + 33, FULLN);
    float4* dst = out + (long)b * FULLN * E4 + t;
    for (int n = nlo; n < nhi; n++)
        dst[(long)n * E4] = s;
}

// ================================================================
extern "C" void kernel_launch(void* const* d_in, const int* in_sizes, int n_in,
                              void* d_out, int out_size)
{
    const float* x    = (const float*)d_in[0];
    const float* bio  = (const float*)d_in[1];
    const float* base = (const float*)d_in[2];
    const float* off  = (const float*)d_in[3];
    const float* conf = (const float*)d_in[4];
    const float* Ws   = (const float*)d_in[5];
    const float* bs   = (const float*)d_in[6];
    const float* Win  = (const float*)d_in[7];
    const float* bin  = (const float*)d_in[8];
    const float* Wo   = (const float*)d_in[9];
    const float* bo   = (const float*)d_in[10];
    float* out = (float*)d_out;

    float *sampled, *T, *TK, *part, *partq;
    cudaGetSymbolAddress((void**)&sampled, g_sampled);
    cudaGetSymbolAddress((void**)&T,     g_T);
    cudaGetSymbolAddress((void**)&TK,    g_TK);
    cudaGetSymbolAddress((void**)&part,  g_part);
    cudaGetSymbolAddress((void**)&partq, g_partq);

    __nv_bfloat16 *ext1, *Uext, *Wsext, *Wstext, *Wq, *Wv, *Wox, *bioext, *ctxext;
    cudaGetSymbolAddress((void**)&ext1,   g_ext1);
    cudaGetSymbolAddress((void**)&Uext,   g_Uext);
    cudaGetSymbolAddress((void**)&Wsext,  g_Wsext);
    cudaGetSymbolAddress((void**)&Wstext, g_Wstext);
    cudaGetSymbolAddress((void**)&Wq,     g_Wq);
    cudaGetSymbolAddress((void**)&Wv,     g_Wv);
    cudaGetSymbolAddress((void**)&Wox,    g_Wo);
    cudaGetSymbolAddress((void**)&bioext, g_bioext);
    cudaGetSymbolAddress((void**)&ctxext, g_ctxext);

    cudaFuncSetAttribute(hmma_kernel,
                         cudaFuncAttributeMaxDynamicSharedMemorySize, SMEM2);

    const long spl = (long)B_ * E_;

    // 1) trilinear sample
    sample_kernel<<<B_ * NB, 192>>>(x, base, off, sampled);

    // 2) all conversions, one launch
    prep_all_kernel<<<dim3(24, 24, 5), 256>>>(
        Ws, Win, Wo, bio, Wsext, Wstext, Wq, Wv, Wox, bioext);

    // 3) q partials = bio @ Wq.T  (split-K=4; reduce fused into consumers)
    hmma_kernel<<<dim3(12, 1, 4), 256, SMEM2>>>(
        bioext, KE, 0, Wq, 0, nullptr, partq, nullptr, 0, 4, KE, spl);

    // 4) T_h = q_h @ Wk_h  (q reduced inline) -> T fp32 + T ext; 288 CTAs
    qk_head_kernel<<<dim3(24, H_), 256>>>(partq, bin, Win + E_ * E_, T, ext1);

    // 5) TK = T @ Ws  (big HMMA)
    hmma_kernel<<<dim3(12, 12, 1), 256, SMEM2>>>(
        ext1, KE, 0, Wstext, 0, nullptr, TK, nullptr, 0, 1, KE, 0);

    // 6) scores + softmax + US-ext (fused, per-bh)
    scores_us_kernel<<<BH, 128>>>(TK, T, partq, sampled, bin, bs, ext1);

    // 7) U = US @ Ws.T + bs  (big HMMA) -> U ext
    hmma_kernel<<<dim3(12, 12, 1), 256, SMEM2>>>(
        ext1, KE, 0, Wsext, 0, bs, nullptr, Uext, 0, 1, KE, 0);

    // 8) ctx_h = U_h @ Wv_h.T  (per-head, split-K=4) + reduce -> ctx ext
    hmma_kernel<<<dim3(1, 1, H_ * 4), 256, SMEM2>>>(
        Uext, (long)H_ * KE, KE, Wv, (long)HD * KE,
        nullptr, part, nullptr, HD, 4, KE, spl);
    reduce2_kernel<<<48, 256>>>(part, bin + 2 * E_, nullptr, ctxext, 4);

    // 9) ao partials = ctx @ Wo.T  (split-K=4; reduce fused into out)
    hmma_kernel<<<dim3(12, 1, 4), 256, SMEM2>>>(
        ctxext, KE, 0, Wox, 0, nullptr, part, nullptr, 0, 4, KE, spl);

    // 10) out = (reduce(ao) + bo) * confidence, broadcast over N
    out_kernel<<<dim3(ONS, B_), 192>>>(part, bo, conf, (float4*)out);
}

// round 15
// speedup vs baseline: 1.1509x; 1.0345x over previous
#include <cuda_runtime.h>
#include <cuda_bf16.h>
#include <math.h>
#include <stdint.h>

#define B_    64
#define FULLN 513
#define E_    768
#define NB    32
#define H_    12
#define HD    64
#define BH    (B_ * H_)       // 768
#define E4    (E_ / 4)        // 192
#define KE    2304            // extended K = 3 * 768

// -------- scratch (device globals; no allocation allowed) --------
__device__ float g_sampled[B_ * NB * E_];
__device__ float g_T[BH * E_];
__device__ float g_partq[4 * B_ * E_];       // q split-K partials
__device__ float g_part[4 * B_ * E_];        // ctx / ao split-K partials
__device__ float g_partBig[2 * BH * E_];     // TK split-K partials

// bf16 extended operands.  A-mode segments: (hi, lo, hi); B-mode: (hi, hi, lo)
__device__ __nv_bfloat16 g_ext1[E_ * KE];    // T-ext, then US-ext (A-mode, reused)
__device__ __nv_bfloat16 g_Uext[E_ * KE];    // U-ext (A-mode)
__device__ __nv_bfloat16 g_Wsext[E_ * KE];   // Ws rows   (B-mode)
__device__ __nv_bfloat16 g_Wstext[E_ * KE];  // Ws^T rows (B-mode)
__device__ __nv_bfloat16 g_Wq[E_ * KE];      // Wq rows (B-mode)
__device__ __nv_bfloat16 g_Wv[E_ * KE];      // Wv rows (B-mode)
__device__ __nv_bfloat16 g_Wo[E_ * KE];      // Wo rows (B-mode)
__device__ __nv_bfloat16 g_bioext[B_ * KE];  // bio (A-mode)
__device__ __nv_bfloat16 g_ctxext[B_ * KE];  // ctx (A-mode)

// ================= helpers =================
__device__ __forceinline__ uint32_t smem_u32(const void* p) {
    uint32_t a;
    asm("{ .reg .u64 t; cvta.to.shared.u64 t, %1; cvt.u32.u64 %0, t; }" : "=r"(a) : "l"(p));
    return a;
}
__device__ __forceinline__ void ldsm_x4(uint32_t addr, uint32_t& r0, uint32_t& r1,
                                        uint32_t& r2, uint32_t& r3) {
    asm volatile("ldmatrix.sync.aligned.m8n8.x4.shared.b16 {%0,%1,%2,%3}, [%4];"
                 : "=r"(r0), "=r"(r1), "=r"(r2), "=r"(r3) : "r"(addr));
}
__device__ __forceinline__ void mma16816(float* d, const uint32_t* a, const uint32_t* b) {
    asm volatile("mma.sync.aligned.m16n8k16.row.col.f32.bf16.bf16.f32 "
                 "{%0,%1,%2,%3}, {%4,%5,%6,%7}, {%8,%9}, {%0,%1,%2,%3};"
                 : "+f"(d[0]), "+f"(d[1]), "+f"(d[2]), "+f"(d[3])
                 : "r"(a[0]), "r"(a[1]), "r"(a[2]), "r"(a[3]), "r"(b[0]), "r"(b[1]));
}
__device__ __forceinline__ void st_hilo_pair(__nv_bfloat16* base, float x, float y) {
    __nv_bfloat16 hx = __float2bfloat16(x), hy = __float2bfloat16(y);
    __nv_bfloat16 lx = __float2bfloat16(x - __bfloat162float(hx));
    __nv_bfloat16 ly = __float2bfloat16(y - __bfloat162float(hy));
    __nv_bfloat162 hp; hp.x = hx; hp.y = hy;
    __nv_bfloat162 lp; lp.x = lx; lp.y = ly;
    *(__nv_bfloat162*)(base) = hp;
    *(__nv_bfloat162*)(base + E_) = lp;
    *(__nv_bfloat162*)(base + 2 * E_) = hp;
}
#define CP16(saddr, gptr) \
    asm volatile("cp.async.ca.shared.global [%0], [%1], 16;" \
                 :: "r"(saddr), "l"(gptr))
#define CP_COMMIT() asm volatile("cp.async.commit_group;")
#define CP_WAIT1()  asm volatile("cp.async.wait_group 1;")
#define CP_WAIT0()  asm volatile("cp.async.wait_group 0;")

// ================= HMMA GEMM: CH=64, cp.async, 3-buffer pipeline ===========
#define CH2   64
#define ROW2  144
#define TILE2 (64 * ROW2)
#define OPS2  (2 * TILE2)
#define SMEM2 (3 * OPS2)          // 55296

__global__ void __launch_bounds__(256) hmma_kernel(
    const __nv_bfloat16* __restrict__ Aext, long lda, long sAz,
    const __nv_bfloat16* __restrict__ Bext, long sBz,
    const float* __restrict__ bias,
    float* __restrict__ Cout, __nv_bfloat16* __restrict__ extOut,
    int nOffMul, int nSplit, int kLen, long splitStride)
{
    extern __shared__ __align__(16) char smem[];
    const int tid = threadIdx.x;
    const int w = tid >> 5, lane = tid & 31;
    const int m0 = blockIdx.y * 64;
    const int n0 = blockIdx.x * 64;
    const int zb = blockIdx.z / nSplit;
    const int sp = blockIdx.z - zb * nSplit;
    const int wm = w & 1, wn = w >> 1;
    const uint32_t sbase = smem_u32(smem);

    const int kcl  = kLen / nSplit;
    const int cnum = kcl / CH2;

    const int r  = tid >> 3;
    const int sg = tid & 7;
    const __nv_bfloat16* gA = Aext + zb * sAz + (long)(m0 + r) * lda + (long)sp * kcl + sg * 8;
    const __nv_bfloat16* gB = Bext + zb * sBz + (long)(n0 + r) * KE  + (long)sp * kcl + sg * 8;
    const uint32_t stA = (uint32_t)(r * ROW2 + sg * 16);
    const uint32_t stB = TILE2 + stA;
    const long gA32 = 32 * lda;
    const long gB32 = (long)32 * KE;

#define ISSUE(c) do { \
        uint32_t bb = sbase + ((c) % 3) * OPS2; \
        const __nv_bfloat16* pa = gA + (long)(c) * CH2; \
        const __nv_bfloat16* pb = gB + (long)(c) * CH2; \
        CP16(bb + stA,             pa); \
        CP16(bb + stA + 32 * ROW2, pa + gA32); \
        CP16(bb + stB,             pb); \
        CP16(bb + stB + 32 * ROW2, pb + gB32); \
        CP_COMMIT(); \
    } while (0)

    float acc[2][2][4];
#pragma unroll
    for (int i = 0; i < 2; i++)
#pragma unroll
        for (int j = 0; j < 2; j++)
#pragma unroll
            for (int v = 0; v < 4; v++) acc[i][j][v] = 0.f;

    ISSUE(0);
    ISSUE(1);

    const int qq = lane >> 3, r8 = lane & 7;
    const uint32_t aoff = (uint32_t)((wm * 32 + (qq & 1) * 8 + r8) * ROW2 + ((qq >> 1) * 8) * 2);
    const uint32_t boff = (uint32_t)(TILE2 + (wn * 16 + (qq >> 1) * 8 + r8) * ROW2 + ((qq & 1) * 8) * 2);

    for (int c = 0; c < cnum; c++) {
        if (c + 1 < cnum) CP_WAIT1(); else CP_WAIT0();
        __syncthreads();
        if (c + 2 < cnum) ISSUE(c + 2);
        const uint32_t base = sbase + (c % 3) * OPS2;
#pragma unroll
        for (int s = 0; s < 4; s++) {
            uint32_t af0[4], af1[4], bf[4];
            ldsm_x4(base + boff + s * 32, bf[0], bf[1], bf[2], bf[3]);
            ldsm_x4(base + aoff + s * 32, af0[0], af0[1], af0[2], af0[3]);
            ldsm_x4(base + aoff + 16 * ROW2 + s * 32, af1[0], af1[1], af1[2], af1[3]);
            mma16816(acc[0][0], af0, bf + 0);
            mma16816(acc[0][1], af0, bf + 2);
            mma16816(acc[1][0], af1, bf + 0);
            mma16816(acc[1][1], af1, bf + 2);
        }
    }
#undef ISSUE

    float* Cp = Cout ? (Cout + (long)sp * splitStride) : nullptr;
    const int col0 = n0 + zb * nOffMul;
    const int gr = lane >> 2, gc = (lane & 3) * 2;
#pragma unroll
    for (int mi = 0; mi < 2; mi++) {
#pragma unroll
        for (int ni = 0; ni < 2; ni++) {
            int rr = m0 + wm * 32 + mi * 16 + gr;
            int cc = col0 + wn * 16 + ni * 8 + gc;
            float bx = 0.f, by = 0.f;
            if (nSplit == 1 && bias) { bx = bias[cc]; by = bias[cc + 1]; }
            float x0 = acc[mi][ni][0] + bx, y0 = acc[mi][ni][1] + by;
            float x1 = acc[mi][ni][2] + bx, y1 = acc[mi][ni][3] + by;
            if (Cp) {
                *(float2*)(Cp + (long)rr * E_ + cc) = make_float2(x0, y0);
                *(float2*)(Cp + (long)(rr + 8) * E_ + cc) = make_float2(x1, y1);
            }
            if (nSplit == 1 && extOut) {
                st_hilo_pair(extOut + (long)rr * KE + cc, x0, y0);
                st_hilo_pair(extOut + (long)(rr + 8) * KE + cc, x1, y1);
            }
        }
    }
}

// ================= split-K reduce (ctx only) =================
__global__ void __launch_bounds__(256) reduce2_kernel(
    const float* __restrict__ part, const float* __restrict__ bias,
    float* __restrict__ Cout, __nv_bfloat16* __restrict__ extOut, int nSplit)
{
    const int total4 = B_ * E4;
    int i = blockIdx.x * blockDim.x + threadIdx.x;
    if (i >= total4) return;
    const float4* P = reinterpret_cast<const float4*>(part);
    float4 s = P[i];
    for (int sp = 1; sp < nSplit; sp++) {
        float4 v = P[(long)sp * total4 + i];
        s.x += v.x; s.y += v.y; s.z += v.z; s.w += v.w;
    }
    int rr = i / E4;
    int cc = (i - rr * E4) * 4;
    if (bias) {
        float4 b = *(const float4*)(bias + cc);
        s.x += b.x; s.y += b.y; s.z += b.z; s.w += b.w;
    }
    if (Cout) reinterpret_cast<float4*>(Cout)[i] = s;
    if (extOut) {
        __nv_bfloat16* e = extOut + (long)rr * KE + cc;
        st_hilo_pair(e, s.x, s.y);
        st_hilo_pair(e + 2, s.z, s.w);
    }
}

// ====== merged prep_all + trilinear sample (one launch) ======
// flat grid: blocks [0, 2880) = prep (24 x 24 x 5); blocks [2880, 4928) = sample.
#define PREP_BLOCKS 2880
#define MERGED_BLOCKS (PREP_BLOCKS + B_ * NB)

__global__ void __launch_bounds__(256) prep_sample_kernel(
    const float* __restrict__ Ws, const float* __restrict__ Win,
    const float* __restrict__ Wo, const float* __restrict__ bio,
    __nv_bfloat16* __restrict__ wsext, __nv_bfloat16* __restrict__ wstext,
    __nv_bfloat16* __restrict__ wq, __nv_bfloat16* __restrict__ wv,
    __nv_bfloat16* __restrict__ wox, __nv_bfloat16* __restrict__ bioext,
    const float* __restrict__ x, const float* __restrict__ base,
    const float* __restrict__ off, float* __restrict__ sampled)
{
    const int bid = blockIdx.x;
    if (bid >= PREP_BLOCKS) {
        // ---------------- trilinear sample path ----------------
        const int t = threadIdx.x;
        if (t >= 192) return;
        const int bp = bid - PREP_BLOCKS;
        const int b = bp >> 5, p = bp & 31;

        float cx = fminf(fmaxf(base[p * 3 + 0] + off[bp * 3 + 0], -1.f), 1.f);
        float cy = fminf(fmaxf(base[p * 3 + 1] + off[bp * 3 + 1], -1.f), 1.f);
        float cz = fminf(fmaxf(base[p * 3 + 2] + off[bp * 3 + 2], -1.f), 1.f);

        float ix = (cx + 1.f) * 3.5f;
        float iy = (cy + 1.f) * 3.5f;
        float iz = (cz + 1.f) * 3.5f;
        float fx = floorf(ix), fy = floorf(iy), fz = floorf(iz);
        float wx = ix - fx, wy = iy - fy, wz = iz - fz;
        int x0 = max(0, min(7, (int)fx));
        int y0 = max(0, min(7, (int)fy));
        int z0 = max(0, min(7, (int)fz));
        int x1 = min(7, x0 + 1), y1 = min(7, y0 + 1), z1 = min(7, z0 + 1);

        int r000 = 1 + ((z0 * 8 + y0) * 8 + x0);
        int r001 = 1 + ((z0 * 8 + y0) * 8 + x1);
        int r010 = 1 + ((z0 * 8 + y1) * 8 + x0);
        int r011 = 1 + ((z0 * 8 + y1) * 8 + x1);
        int r100 = 1 + ((z1 * 8 + y0) * 8 + x0);
        int r101 = 1 + ((z1 * 8 + y0) * 8 + x1);
        int r110 = 1 + ((z1 * 8 + y1) * 8 + x0);
        int r111 = 1 + ((z1 * 8 + y1) * 8 + x1);

        float w000 = (1.f - wz) * (1.f - wy) * (1.f - wx);
        float w001 = (1.f - wz) * (1.f - wy) * wx;
        float w010 = (1.f - wz) * wy * (1.f - wx);
        float w011 = (1.f - wz) * wy * wx;
        float w100 = wz * (1.f - wy) * (1.f - wx);
        float w101 = wz * (1.f - wy) * wx;
        float w110 = wz * wy * (1.f - wx);
        float w111 = wz * wy * wx;

        const float4* X = reinterpret_cast<const float4*>(x) + (long)b * FULLN * E4;
        float4 s = make_float4(0.f, 0.f, 0.f, 0.f);
#define ACC(R, W) { float4 v = X[(R) * E4 + t]; \
            s.x = fmaf(W, v.x, s.x); s.y = fmaf(W, v.y, s.y); \
            s.z = fmaf(W, v.z, s.z); s.w = fmaf(W, v.w, s.w); }
        ACC(r000, w000) ACC(r001, w001) ACC(r010, w010) ACC(r011, w011)
        ACC(r100, w100) ACC(r101, w101) ACC(r110, w110) ACC(r111, w111)
#undef ACC
        reinterpret_cast<float4*>(sampled)[(long)bp * E4 + t] = s;
        return;
    }

    // ---------------- prep path ----------------
    __shared__ float tile[32][33];
    const int z = bid / 576;
    const int rem = bid - z * 576;
    const int bx = (rem % 24) * 32;
    const int by = (rem / 24) * 32;
    const int tx = threadIdx.x & 31, ty = threadIdx.x >> 5;

    if (z == 0) {
#pragma unroll
        for (int j = 0; j < 4; j++) {
            float xv = Ws[(long)(by + ty + 8 * j) * E_ + bx + tx];
            tile[ty + 8 * j][tx] = xv;
            __nv_bfloat16 h = __float2bfloat16(xv);
            __nv_bfloat16 l = __float2bfloat16(xv - __bfloat162float(h));
            __nv_bfloat16* o = wsext + (long)(by + ty + 8 * j) * KE + bx + tx;
            o[0] = h; o[E_] = h; o[2 * E_] = l;
        }
        __syncthreads();
#pragma unroll
        for (int j = 0; j < 4; j++) {
            float xv = tile[tx][ty + 8 * j];
            __nv_bfloat16 h = __float2bfloat16(xv);
            __nv_bfloat16 l = __float2bfloat16(xv - __bfloat162float(h));
            __nv_bfloat16* o = wstext + (long)(bx + ty + 8 * j) * KE + by + tx;
            o[0] = h; o[E_] = h; o[2 * E_] = l;
        }
    } else if (z <= 3) {
        const float* s = (z == 1) ? Win : (z == 2) ? (Win + 2 * E_ * E_) : Wo;
        __nv_bfloat16* d = (z == 1) ? wq : (z == 2) ? wv : wox;
#pragma unroll
        for (int j = 0; j < 4; j++) {
            int rr = by + ty + 8 * j;
            float xv = s[(long)rr * E_ + bx + tx];
            __nv_bfloat16 h = __float2bfloat16(xv);
            __nv_bfloat16 l = __float2bfloat16(xv - __bfloat162float(h));
            __nv_bfloat16* o = d + (long)rr * KE + bx + tx;
            o[0] = h; o[E_] = h; o[2 * E_] = l;
        }
    } else {
        if (by >= B_) return;
#pragma unroll
        for (int j = 0; j < 4; j++) {
            int rr = by + ty + 8 * j;
            if (rr >= B_) continue;
            float xv = bio[(long)rr * E_ + bx + tx];
            __nv_bfloat16 h = __float2bfloat16(xv);
            __nv_bfloat16 l = __float2bfloat16(xv - __bfloat162float(h));
            __nv_bfloat16* o = bioext + (long)rr * KE + bx + tx;
            o[0] = h; o[E_] = l; o[2 * E_] = h;
        }
    }
}

// ===== T_h = q_h @ Wk_h (K=64), q from 4-way partials + bq; ext epilogue ====
__global__ void __launch_bounds__(256) qk_head_kernel(
    const float* __restrict__ partq, const float* __restrict__ bin,
    const float* __restrict__ Wk,
    float* __restrict__ T, __nv_bfloat16* __restrict__ Text)
{
    __shared__ __align__(16) float As[64][68];
    __shared__ __align__(16) float Bs[64][68];
    const int tid = threadIdx.x;
    const int n0 = blockIdx.x * 64;
    const int h = blockIdx.y;
    const long spl = (long)B_ * E_;

    const int r = tid >> 2, cbase = (tid & 3) * 16;
#pragma unroll
    for (int j = 0; j < 4; j++) {
        int c4 = cbase + j * 4;
        long qo = (long)r * E_ + h * HD + c4;
        float4 a = *(const float4*)(partq + qo);
#pragma unroll
        for (int sp = 1; sp < 4; sp++) {
            float4 v = *(const float4*)(partq + sp * spl + qo);
            a.x += v.x; a.y += v.y; a.z += v.z; a.w += v.w;
        }
        float4 bq = *(const float4*)(bin + h * HD + c4);
        a.x += bq.x; a.y += bq.y; a.z += bq.z; a.w += bq.w;
        As[c4 + 0][r] = a.x; As[c4 + 1][r] = a.y;
        As[c4 + 2][r] = a.z; As[c4 + 3][r] = a.w;
        float4 b = *(const float4*)(Wk + (long)(h * HD + r) * E_ + n0 + c4);
        *(float4*)(&Bs[r][c4]) = b;
    }
    __syncthreads();

    const int ty = tid >> 4, tx = tid & 15;
    float acc[4][4];
#pragma unroll
    for (int i = 0; i < 4; i++)
#pragma unroll
        for (int j = 0; j < 4; j++) acc[i][j] = 0.f;

#pragma unroll 8
    for (int k = 0; k < 64; k++) {
        float4 av = *(const float4*)(&As[k][ty * 4]);
        float4 bv = *(const float4*)(&Bs[k][tx * 4]);
        float a[4] = {av.x, av.y, av.z, av.w};
        float b[4] = {bv.x, bv.y, bv.z, bv.w};
#pragma unroll
        for (int i = 0; i < 4; i++)
#pragma unroll
            for (int j = 0; j < 4; j++)
                acc[i][j] = fmaf(a[i], b[j], acc[i][j]);
    }

#pragma unroll
    for (int i = 0; i < 4; i++) {
        int b = ty * 4 + i;
        long bh = (long)b * H_ + h;
#pragma unroll
        for (int j = 0; j < 4; j += 2) {
            int n = n0 + tx * 4 + j;
            float x0 = acc[i][j], x1 = acc[i][j + 1];
            *(float2*)(T + bh * E_ + n) = make_float2(x0, x1);
            st_hilo_pair(Text + bh * KE + n, x0, x1);
        }
    }
}

// ====== fused scores + softmax + US-ext (per-bh; TK from 2 partials) =======
__global__ void __launch_bounds__(128) scores_us_kernel(
    const float* __restrict__ partTK, const float* __restrict__ T,
    const float* __restrict__ partq, const float* __restrict__ sampled,
    const float* __restrict__ in_proj_b, const float* __restrict__ bs,
    __nv_bfloat16* __restrict__ ext)
{
    int bh = blockIdx.x;
    int b = bh / H_, h = bh % H_;
    __shared__ float tk[E_];
    __shared__ float sc[NB];
    __shared__ float red[4];
    __shared__ float cbs;
    int tid = threadIdx.x;
    int w = tid >> 5, lane = tid & 31;
    const long spl = (long)B_ * E_;
    const long splTK = (long)BH * E_;

    const float* TKrow  = partTK + (long)bh * E_;
    const float* TKrow2 = partTK + splTK + (long)bh * E_;
    const float* Trow   = T + (long)bh * E_;
    float part = 0.f;
    for (int f = tid; f < E_; f += 128) {
        float t = TKrow[f] + TKrow2[f];
        tk[f] = t;
        part += Trow[f] * bs[f];
    }
    if (tid < HD) {
        long qo = (long)b * E_ + h * HD + tid;
        float qv = partq[qo] + partq[spl + qo] + partq[2 * spl + qo] + partq[3 * spl + qo]
                 + in_proj_b[h * HD + tid];
        part += qv * in_proj_b[E_ + h * HD + tid];
    }
#pragma unroll
    for (int o = 16; o; o >>= 1) part += __shfl_xor_sync(0xffffffffu, part, o);
    if (lane == 0) red[w] = part;
    __syncthreads();
    if (tid == 0) cbs = red[0] + red[1] + red[2] + red[3];
    __syncthreads();

    float cb = cbs;
#pragma unroll
    for (int pi = 0; pi < 8; pi++) {
        int p = w * 8 + pi;
        const float* srow = sampled + ((long)b * NB + p) * E_;
        float d = 0.f;
        for (int f = lane; f < E_; f += 32) d = fmaf(tk[f], srow[f], d);
#pragma unroll
        for (int o = 16; o; o >>= 1) d += __shfl_xor_sync(0xffffffffu, d, o);
        if (lane == 0) sc[p] = (d + cb) * 0.125f;
    }
    __syncthreads();
    if (tid < NB) {
        float s = sc[tid];
        float m = s;
#pragma unroll
        for (int o = 16; o; o >>= 1) m = fmaxf(m, __shfl_xor_sync(0xffffffffu, m, o));
        float e = expf(s - m);
        float sum = e;
#pragma unroll
        for (int o = 16; o; o >>= 1) sum += __shfl_xor_sync(0xffffffffu, sum, o);
        sc[tid] = e / sum;
    }
    __syncthreads();

    const float4* S = reinterpret_cast<const float4*>(sampled) + (long)b * NB * E4;
    for (int f = tid; f < E4; f += 128) {
        float4 acc = make_float4(0.f, 0.f, 0.f, 0.f);
#pragma unroll 8
        for (int p = 0; p < NB; p++) {
            float wv = sc[p];
            float4 s = S[p * E4 + f];
            acc.x = fmaf(wv, s.x, acc.x); acc.y = fmaf(wv, s.y, acc.y);
            acc.z = fmaf(wv, s.z, acc.z); acc.w = fmaf(wv, s.w, acc.w);
        }
        __nv_bfloat16* e = ext + (long)bh * KE + 4 * f;
        st_hilo_pair(e, acc.x, acc.y);
        st_hilo_pair(e + 2, acc.z, acc.w);
    }
}

// ====== broadcast out: fused ao split-K reduce + bias + confidence =========
#define ONS 16
__global__ void __launch_bounds__(192) out_kernel(
    const float* __restrict__ part, const float* __restrict__ bo,
    const float* __restrict__ conf, float4* __restrict__ out)
{
    const int b = blockIdx.y, t = threadIdx.x;
    const long spl = (long)B_ * E_;
    long o = (long)b * E_ + 4 * t;
    float4 s = *(const float4*)(part + o);
#pragma unroll
    for (int sp = 1; sp < 4; sp++) {
        float4 v = *(const float4*)(part + sp * spl + o);
        s.x += v.x; s.y += v.y; s.z += v.z; s.w += v.w;
    }
    float4 bb = *(const float4*)(bo + 4 * t);
    float cf = conf[b];
    s.x = (s.x + bb.x) * cf; s.y = (s.y + bb.y) * cf;
    s.z = (s.z + bb.z) * cf; s.w = (s.w + bb.w) * cf;

    const int nlo = blockIdx.x * 33;
    const int nhi = min(nlo + 33, FULLN);
    float4* dst = out + (long)b * FULLN * E4 + t;
    for (int n = nlo; n < nhi; n++)
        dst[(long)n * E4] = s;
}

// ================================================================
extern "C" void kernel_launch(void* const* d_in, const int* in_sizes, int n_in,
                              void* d_out, int out_size)
{
    const float* x    = (const float*)d_in[0];
    const float* bio  = (const float*)d_in[1];
    const float* base = (const float*)d_in[2];
    const float* off  = (const float*)d_in[3];
    const float* conf = (const float*)d_in[4];
    const float* Ws   = (const float*)d_in[5];
    const float* bs   = (const float*)d_in[6];
    const float* Win  = (const float*)d_in[7];
    const float* bin  = (const float*)d_in[8];
    const float* Wo   = (const float*)d_in[9];
    const float* bo   = (const float*)d_in[10];
    float* out = (float*)d_out;

    float *sampled, *T, *part, *partq, *partBig;
    cudaGetSymbolAddress((void**)&sampled, g_sampled);
    cudaGetSymbolAddress((void**)&T,       g_T);
    cudaGetSymbolAddress((void**)&part,    g_part);
    cudaGetSymbolAddress((void**)&partq,   g_partq);
    cudaGetSymbolAddress((void**)&partBig, g_partBig);

    __nv_bfloat16 *ext1, *Uext, *Wsext, *Wstext, *Wq, *Wv, *Wox, *bioext, *ctxext;
    cudaGetSymbolAddress((void**)&ext1,   g_ext1);
    cudaGetSymbolAddress((void**)&Uext,   g_Uext);
    cudaGetSymbolAddress((void**)&Wsext,  g_Wsext);
    cudaGetSymbolAddress((void**)&Wstext, g_Wstext);
    cudaGetSymbolAddress((void**)&Wq,     g_Wq);
    cudaGetSymbolAddress((void**)&Wv,     g_Wv);
    cudaGetSymbolAddress((void**)&Wox,    g_Wo);
    cudaGetSymbolAddress((void**)&bioext, g_bioext);
    cudaGetSymbolAddress((void**)&ctxext, g_ctxext);

    cudaFuncSetAttribute(hmma_kernel,
                         cudaFuncAttributeMaxDynamicSharedMemorySize, SMEM2);

    const long spl    = (long)B_ * E_;
    const long splBig = (long)BH * E_;

    // 1) merged: all conversions + trilinear sample (one launch)
    prep_sample_kernel<<<MERGED_BLOCKS, 256>>>(
        Ws, Win, Wo, bio, Wsext, Wstext, Wq, Wv, Wox, bioext,
        x, base, off, sampled);

    // 2) q partials = bio @ Wq.T  (split-K=4; reduce fused into consumers)
    hmma_kernel<<<dim3(12, 1, 4), 256, SMEM2>>>(
        bioext, KE, 0, Wq, 0, nullptr, partq, nullptr, 0, 4, KE, spl);

    // 3) T_h = q_h @ Wk_h  (q reduced inline) -> T fp32 + T ext
    qk_head_kernel<<<dim3(12, H_), 256>>>(partq, bin, Win + E_ * E_, T, ext1);

    // 4) TK partials = T @ Ws  (split-K=2; reduce fused into scores_us)
    hmma_kernel<<<dim3(12, 12, 2), 256, SMEM2>>>(
        ext1, KE, 0, Wstext, 0, nullptr, partBig, nullptr, 0, 2, KE, splBig);

    // 5) scores + softmax + US-ext (fused, per-bh; sums TK partials inline)
    scores_us_kernel<<<BH, 128>>>(partBig, T, partq, sampled, bin, bs, ext1);

    // 6) U = US @ Ws.T + bs  (big HMMA, nSplit=1) -> U ext
    hmma_kernel<<<dim3(12, 12, 1), 256, SMEM2>>>(
        ext1, KE, 0, Wsext, 0, bs, nullptr, Uext, 0, 1, KE, 0);

    // 7) ctx_h = U_h @ Wv_h.T  (per-head, split-K=4) + reduce -> ctx ext
    hmma_kernel<<<dim3(1, 1, H_ * 4), 256, SMEM2>>>(
        Uext, (long)H_ * KE, KE, Wv, (long)HD * KE,
        nullptr, part, nullptr, HD, 4, KE, spl);
    reduce2_kernel<<<48, 256>>>(part, bin + 2 * E_, nullptr, ctxext, 4);

    // 8) ao partials = ctx @ Wo.T  (split-K=4; reduce fused into out)
    hmma_kernel<<<dim3(12, 1, 4), 256, SMEM2>>>(
        ctxext, KE, 0, Wox, 0, nullptr, part, nullptr, 0, 4, KE, spl);

    // 9) out = (reduce(ao) + bo) * confidence, broadcast over N
    out_kernel<<<dim3(ONS, B_), 192>>>(part, bo, conf, (float4*)out);
}

// round 16
// speedup vs baseline: 1.1800x; 1.0253x over previous
#include <cuda_runtime.h>
#include <cuda_bf16.h>
#include <math.h>
#include <stdint.h>

#define B_    64
#define FULLN 513
#define E_    768
#define NB    32
#define H_    12
#define HD    64
#define BH    (B_ * H_)       // 768
#define E4    (E_ / 4)        // 192
#define KE    2304            // extended K = 3 * 768

// -------- scratch (device globals; no allocation allowed) --------
__device__ float g_sampled[B_ * NB * E_];
__device__ float g_T[BH * E_];
__device__ float g_partq[4 * B_ * E_];       // q split-K partials
__device__ float g_part[4 * B_ * E_];        // ctx / ao split-K partials
__device__ float g_partBig[2 * BH * E_];     // TK split-K partials

// bf16 extended operands.  A-mode segments: (hi, lo, hi); B-mode: (hi, hi, lo)
__device__ __nv_bfloat16 g_ext1[E_ * KE];    // T-ext, then US-ext (A-mode, reused)
__device__ __nv_bfloat16 g_Uext[E_ * KE];    // U-ext (A-mode)
__device__ __nv_bfloat16 g_Wsext[E_ * KE];   // Ws rows   (B-mode)
__device__ __nv_bfloat16 g_Wstext[E_ * KE];  // Ws^T rows (B-mode)
__device__ __nv_bfloat16 g_Wq[E_ * KE];      // Wq rows (B-mode)
__device__ __nv_bfloat16 g_Wv[E_ * KE];      // Wv rows (B-mode)
__device__ __nv_bfloat16 g_Wo[E_ * KE];      // Wo rows (B-mode)
__device__ __nv_bfloat16 g_bioext[B_ * KE];  // bio (A-mode)
__device__ __nv_bfloat16 g_ctxext[B_ * KE];  // ctx (A-mode)

// ================= helpers =================
__device__ __forceinline__ uint32_t smem_u32(const void* p) {
    uint32_t a;
    asm("{ .reg .u64 t; cvta.to.shared.u64 t, %1; cvt.u32.u64 %0, t; }" : "=r"(a) : "l"(p));
    return a;
}
__device__ __forceinline__ void ldsm_x4(uint32_t addr, uint32_t& r0, uint32_t& r1,
                                        uint32_t& r2, uint32_t& r3) {
    asm volatile("ldmatrix.sync.aligned.m8n8.x4.shared.b16 {%0,%1,%2,%3}, [%4];"
                 : "=r"(r0), "=r"(r1), "=r"(r2), "=r"(r3) : "r"(addr));
}
__device__ __forceinline__ void mma16816(float* d, const uint32_t* a, const uint32_t* b) {
    asm volatile("mma.sync.aligned.m16n8k16.row.col.f32.bf16.bf16.f32 "
                 "{%0,%1,%2,%3}, {%4,%5,%6,%7}, {%8,%9}, {%0,%1,%2,%3};"
                 : "+f"(d[0]), "+f"(d[1]), "+f"(d[2]), "+f"(d[3])
                 : "r"(a[0]), "r"(a[1]), "r"(a[2]), "r"(a[3]), "r"(b[0]), "r"(b[1]));
}
__device__ __forceinline__ void st_hilo_pair(__nv_bfloat16* base, float x, float y) {
    __nv_bfloat16 hx = __float2bfloat16(x), hy = __float2bfloat16(y);
    __nv_bfloat16 lx = __float2bfloat16(x - __bfloat162float(hx));
    __nv_bfloat16 ly = __float2bfloat16(y - __bfloat162float(hy));
    __nv_bfloat162 hp; hp.x = hx; hp.y = hy;
    __nv_bfloat162 lp; lp.x = lx; lp.y = ly;
    *(__nv_bfloat162*)(base) = hp;
    *(__nv_bfloat162*)(base + E_) = lp;
    *(__nv_bfloat162*)(base + 2 * E_) = hp;
}
#define CP16(saddr, gptr) \
    asm volatile("cp.async.ca.shared.global [%0], [%1], 16;" \
                 :: "r"(saddr), "l"(gptr))
#define CP_COMMIT() asm volatile("cp.async.commit_group;")
#define CP_WAIT1()  asm volatile("cp.async.wait_group 1;")
#define CP_WAIT0()  asm volatile("cp.async.wait_group 0;")

// ============ HMMA GEMM: CH=64, cp.async 3-stage, 4 warps of 32x32 =========
#define CH2   64
#define ROW2  144
#define TILE2 (64 * ROW2)
#define OPS2  (2 * TILE2)
#define SMEM2 (3 * OPS2)          // 55296

__global__ void __launch_bounds__(128) hmma_kernel(
    const __nv_bfloat16* __restrict__ Aext, long lda, long sAz,
    const __nv_bfloat16* __restrict__ Bext, long sBz,
    const float* __restrict__ bias,
    float* __restrict__ Cout, __nv_bfloat16* __restrict__ extOut,
    int nOffMul, int nSplit, int kLen, long splitStride)
{
    extern __shared__ __align__(16) char smem[];
    const int tid = threadIdx.x;
    const int w = tid >> 5, lane = tid & 31;
    const int m0 = blockIdx.y * 64;
    const int n0 = blockIdx.x * 64;
    const int zb = blockIdx.z / nSplit;
    const int sp = blockIdx.z - zb * nSplit;
    const int wm = w & 1, wn = w >> 1;    // 2 x 2 warp grid, 32x32 tiles
    const uint32_t sbase = smem_u32(smem);

    const int kcl  = kLen / nSplit;
    const int cnum = kcl / CH2;

    // cp.async: 128 threads; thread covers rows r, r+16, r+32, r+48 (A and B)
    const int r  = tid >> 3;          // 0..15
    const int sg = tid & 7;
    const __nv_bfloat16* gA = Aext + zb * sAz + (long)(m0 + r) * lda + (long)sp * kcl + sg * 8;
    const __nv_bfloat16* gB = Bext + zb * sBz + (long)(n0 + r) * KE  + (long)sp * kcl + sg * 8;
    const uint32_t stA = (uint32_t)(r * ROW2 + sg * 16);
    const uint32_t stB = TILE2 + stA;

#define ISSUE(c) do { \
        uint32_t bb = sbase + ((c) % 3) * OPS2; \
        const __nv_bfloat16* pa = gA + (long)(c) * CH2; \
        const __nv_bfloat16* pb = gB + (long)(c) * CH2; \
        CP16(bb + stA,              pa); \
        CP16(bb + stA + 16 * ROW2,  pa + 16 * lda); \
        CP16(bb + stA + 32 * ROW2,  pa + 32 * lda); \
        CP16(bb + stA + 48 * ROW2,  pa + 48 * lda); \
        CP16(bb + stB,              pb); \
        CP16(bb + stB + 16 * ROW2,  pb + (long)16 * KE); \
        CP16(bb + stB + 32 * ROW2,  pb + (long)32 * KE); \
        CP16(bb + stB + 48 * ROW2,  pb + (long)48 * KE); \
        CP_COMMIT(); \
    } while (0)

    float acc[2][4][4];
#pragma unroll
    for (int i = 0; i < 2; i++)
#pragma unroll
        for (int j = 0; j < 4; j++)
#pragma unroll
            for (int v = 0; v < 4; v++) acc[i][j][v] = 0.f;

    ISSUE(0);
    ISSUE(1);

    const int qq = lane >> 3, r8 = lane & 7;
    // A: 16 rows x 16 k per x4; af0 rows wm*32+0..15, af1 rows +16..31
    const uint32_t aoff = (uint32_t)((wm * 32 + (qq & 1) * 8 + r8) * ROW2 + ((qq >> 1) * 8) * 2);
    // B: 16 cols x 16 k per x4; bf0 cols wn*32+0..15, bf1 cols +16..31
    const uint32_t boff = (uint32_t)(TILE2 + (wn * 32 + (qq >> 1) * 8 + r8) * ROW2 + ((qq & 1) * 8) * 2);

    for (int c = 0; c < cnum; c++) {
        if (c + 1 < cnum) CP_WAIT1(); else CP_WAIT0();
        __syncthreads();
        if (c + 2 < cnum) ISSUE(c + 2);
        const uint32_t base = sbase + (c % 3) * OPS2;
#pragma unroll
        for (int s = 0; s < 4; s++) {
            uint32_t af0[4], af1[4], bf0[4], bf1[4];
            ldsm_x4(base + boff + s * 32, bf0[0], bf0[1], bf0[2], bf0[3]);
            ldsm_x4(base + boff + 16 * ROW2 + s * 32, bf1[0], bf1[1], bf1[2], bf1[3]);
            ldsm_x4(base + aoff + s * 32, af0[0], af0[1], af0[2], af0[3]);
            ldsm_x4(base + aoff + 16 * ROW2 + s * 32, af1[0], af1[1], af1[2], af1[3]);
            mma16816(acc[0][0], af0, bf0 + 0);
            mma16816(acc[0][1], af0, bf0 + 2);
            mma16816(acc[0][2], af0, bf1 + 0);
            mma16816(acc[0][3], af0, bf1 + 2);
            mma16816(acc[1][0], af1, bf0 + 0);
            mma16816(acc[1][1], af1, bf0 + 2);
            mma16816(acc[1][2], af1, bf1 + 0);
            mma16816(acc[1][3], af1, bf1 + 2);
        }
    }
#undef ISSUE

    float* Cp = Cout ? (Cout + (long)sp * splitStride) : nullptr;
    const int col0 = n0 + zb * nOffMul;
    const int gr = lane >> 2, gc = (lane & 3) * 2;
#pragma unroll
    for (int mi = 0; mi < 2; mi++) {
#pragma unroll
        for (int ni = 0; ni < 4; ni++) {
            int rr = m0 + wm * 32 + mi * 16 + gr;
            int cc = col0 + wn * 32 + ni * 8 + gc;
            float bx = 0.f, by = 0.f;
            if (nSplit == 1 && bias) { bx = bias[cc]; by = bias[cc + 1]; }
            float x0 = acc[mi][ni][0] + bx, y0 = acc[mi][ni][1] + by;
            float x1 = acc[mi][ni][2] + bx, y1 = acc[mi][ni][3] + by;
            if (Cp) {
                *(float2*)(Cp + (long)rr * E_ + cc) = make_float2(x0, y0);
                *(float2*)(Cp + (long)(rr + 8) * E_ + cc) = make_float2(x1, y1);
            }
            if (nSplit == 1 && extOut) {
                st_hilo_pair(extOut + (long)rr * KE + cc, x0, y0);
                st_hilo_pair(extOut + (long)(rr + 8) * KE + cc, x1, y1);
            }
        }
    }
}

// ================= split-K reduce (ctx only) =================
__global__ void __launch_bounds__(256) reduce2_kernel(
    const float* __restrict__ part, const float* __restrict__ bias,
    float* __restrict__ Cout, __nv_bfloat16* __restrict__ extOut, int nSplit)
{
    const int total4 = B_ * E4;
    int i = blockIdx.x * blockDim.x + threadIdx.x;
    if (i >= total4) return;
    const float4* P = reinterpret_cast<const float4*>(part);
    float4 s = P[i];
    for (int sp = 1; sp < nSplit; sp++) {
        float4 v = P[(long)sp * total4 + i];
        s.x += v.x; s.y += v.y; s.z += v.z; s.w += v.w;
    }
    int rr = i / E4;
    int cc = (i - rr * E4) * 4;
    if (bias) {
        float4 b = *(const float4*)(bias + cc);
        s.x += b.x; s.y += b.y; s.z += b.z; s.w += b.w;
    }
    if (Cout) reinterpret_cast<float4*>(Cout)[i] = s;
    if (extOut) {
        __nv_bfloat16* e = extOut + (long)rr * KE + cc;
        st_hilo_pair(e, s.x, s.y);
        st_hilo_pair(e + 2, s.z, s.w);
    }
}

// ====== merged prep_all + trilinear sample (one launch) ======
#define PREP_BLOCKS 2880
#define MERGED_BLOCKS (PREP_BLOCKS + B_ * NB)

__global__ void __launch_bounds__(256) prep_sample_kernel(
    const float* __restrict__ Ws, const float* __restrict__ Win,
    const float* __restrict__ Wo, const float* __restrict__ bio,
    __nv_bfloat16* __restrict__ wsext, __nv_bfloat16* __restrict__ wstext,
    __nv_bfloat16* __restrict__ wq, __nv_bfloat16* __restrict__ wv,
    __nv_bfloat16* __restrict__ wox, __nv_bfloat16* __restrict__ bioext,
    const float* __restrict__ x, const float* __restrict__ base,
    const float* __restrict__ off, float* __restrict__ sampled)
{
    const int bid = blockIdx.x;
    if (bid >= PREP_BLOCKS) {
        const int t = threadIdx.x;
        if (t >= 192) return;
        const int bp = bid - PREP_BLOCKS;
        const int b = bp >> 5, p = bp & 31;

        float cx = fminf(fmaxf(base[p * 3 + 0] + off[bp * 3 + 0], -1.f), 1.f);
        float cy = fminf(fmaxf(base[p * 3 + 1] + off[bp * 3 + 1], -1.f), 1.f);
        float cz = fminf(fmaxf(base[p * 3 + 2] + off[bp * 3 + 2], -1.f), 1.f);

        float ix = (cx + 1.f) * 3.5f;
        float iy = (cy + 1.f) * 3.5f;
        float iz = (cz + 1.f) * 3.5f;
        float fx = floorf(ix), fy = floorf(iy), fz = floorf(iz);
        float wx = ix - fx, wy = iy - fy, wz = iz - fz;
        int x0 = max(0, min(7, (int)fx));
        int y0 = max(0, min(7, (int)fy));
        int z0 = max(0, min(7, (int)fz));
        int x1 = min(7, x0 + 1), y1 = min(7, y0 + 1), z1 = min(7, z0 + 1);

        int r000 = 1 + ((z0 * 8 + y0) * 8 + x0);
        int r001 = 1 + ((z0 * 8 + y0) * 8 + x1);
        int r010 = 1 + ((z0 * 8 + y1) * 8 + x0);
        int r011 = 1 + ((z0 * 8 + y1) * 8 + x1);
        int r100 = 1 + ((z1 * 8 + y0) * 8 + x0);
        int r101 = 1 + ((z1 * 8 + y0) * 8 + x1);
        int r110 = 1 + ((z1 * 8 + y1) * 8 + x0);
        int r111 = 1 + ((z1 * 8 + y1) * 8 + x1);

        float w000 = (1.f - wz) * (1.f - wy) * (1.f - wx);
        float w001 = (1.f - wz) * (1.f - wy) * wx;
        float w010 = (1.f - wz) * wy * (1.f - wx);
        float w011 = (1.f - wz) * wy * wx;
        float w100 = wz * (1.f - wy) * (1.f - wx);
        float w101 = wz * (1.f - wy) * wx;
        float w110 = wz * wy * (1.f - wx);
        float w111 = wz * wy * wx;

        const float4* X = reinterpret_cast<const float4*>(x) + (long)b * FULLN * E4;
        float4 s = make_float4(0.f, 0.f, 0.f, 0.f);
#define ACC(R, W) { float4 v = X[(R) * E4 + t]; \
            s.x = fmaf(W, v.x, s.x); s.y = fmaf(W, v.y, s.y); \
            s.z = fmaf(W, v.z, s.z); s.w = fmaf(W, v.w, s.w); }
        ACC(r000, w000) ACC(r001, w001) ACC(r010, w010) ACC(r011, w011)
        ACC(r100, w100) ACC(r101, w101) ACC(r110, w110) ACC(r111, w111)
#undef ACC
        reinterpret_cast<float4*>(sampled)[(long)bp * E4 + t] = s;
        return;
    }

    __shared__ float tile[32][33];
    const int z = bid / 576;
    const int rem = bid - z * 576;
    const int bx = (rem % 24) * 32;
    const int by = (rem / 24) * 32;
    const int tx = threadIdx.x & 31, ty = threadIdx.x >> 5;

    if (z == 0) {
#pragma unroll
        for (int j = 0; j < 4; j++) {
            float xv = Ws[(long)(by + ty + 8 * j) * E_ + bx + tx];
            tile[ty + 8 * j][tx] = xv;
            __nv_bfloat16 h = __float2bfloat16(xv);
            __nv_bfloat16 l = __float2bfloat16(xv - __bfloat162float(h));
            __nv_bfloat16* o = wsext + (long)(by + ty + 8 * j) * KE + bx + tx;
            o[0] = h; o[E_] = h; o[2 * E_] = l;
        }
        __syncthreads();
#pragma unroll
        for (int j = 0; j < 4; j++) {
            float xv = tile[tx][ty + 8 * j];
            __nv_bfloat16 h = __float2bfloat16(xv);
            __nv_bfloat16 l = __float2bfloat16(xv - __bfloat162float(h));
            __nv_bfloat16* o = wstext + (long)(bx + ty + 8 * j) * KE + by + tx;
            o[0] = h; o[E_] = h; o[2 * E_] = l;
        }
    } else if (z <= 3) {
        const float* s = (z == 1) ? Win : (z == 2) ? (Win + 2 * E_ * E_) : Wo;
        __nv_bfloat16* d = (z == 1) ? wq : (z == 2) ? wv : wox;
#pragma unroll
        for (int j = 0; j < 4; j++) {
            int rr = by + ty + 8 * j;
            float xv = s[(long)rr * E_ + bx + tx];
            __nv_bfloat16 h = __float2bfloat16(xv);
            __nv_bfloat16 l = __float2bfloat16(xv - __bfloat162float(h));
            __nv_bfloat16* o = d + (long)rr * KE + bx + tx;
            o[0] = h; o[E_] = h; o[2 * E_] = l;
        }
    } else {
        if (by >= B_) return;
#pragma unroll
        for (int j = 0; j < 4; j++) {
            int rr = by + ty + 8 * j;
            if (rr >= B_) continue;
            float xv = bio[(long)rr * E_ + bx + tx];
            __nv_bfloat16 h = __float2bfloat16(xv);
            __nv_bfloat16 l = __float2bfloat16(xv - __bfloat162float(h));
            __nv_bfloat16* o = bioext + (long)rr * KE + bx + tx;
            o[0] = h; o[E_] = l; o[2 * E_] = h;
        }
    }
}

// ===== T_h = q_h @ Wk_h (K=64), q from 4-way partials + bq; ext epilogue ====
__global__ void __launch_bounds__(256) qk_head_kernel(
    const float* __restrict__ partq, const float* __restrict__ bin,
    const float* __restrict__ Wk,
    float* __restrict__ T, __nv_bfloat16* __restrict__ Text)
{
    __shared__ __align__(16) float As[64][68];
    __shared__ __align__(16) float Bs[64][68];
    const int tid = threadIdx.x;
    const int n0 = blockIdx.x * 64;
    const int h = blockIdx.y;
    const long spl = (long)B_ * E_;

    const int r = tid >> 2, cbase = (tid & 3) * 16;
#pragma unroll
    for (int j = 0; j < 4; j++) {
        int c4 = cbase + j * 4;
        long qo = (long)r * E_ + h * HD + c4;
        float4 a = *(const float4*)(partq + qo);
#pragma unroll
        for (int sp = 1; sp < 4; sp++) {
            float4 v = *(const float4*)(partq + sp * spl + qo);
            a.x += v.x; a.y += v.y; a.z += v.z; a.w += v.w;
        }
        float4 bq = *(const float4*)(bin + h * HD + c4);
        a.x += bq.x; a.y += bq.y; a.z += bq.z; a.w += bq.w;
        As[c4 + 0][r] = a.x; As[c4 + 1][r] = a.y;
        As[c4 + 2][r] = a.z; As[c4 + 3][r] = a.w;
        float4 b = *(const float4*)(Wk + (long)(h * HD + r) * E_ + n0 + c4);
        *(float4*)(&Bs[r][c4]) = b;
    }
    __syncthreads();

    const int ty = tid >> 4, tx = tid & 15;
    float acc[4][4];
#pragma unroll
    for (int i = 0; i < 4; i++)
#pragma unroll
        for (int j = 0; j < 4; j++) acc[i][j] = 0.f;

#pragma unroll 8
    for (int k = 0; k < 64; k++) {
        float4 av = *(const float4*)(&As[k][ty * 4]);
        float4 bv = *(const float4*)(&Bs[k][tx * 4]);
        float a[4] = {av.x, av.y, av.z, av.w};
        float b[4] = {bv.x, bv.y, bv.z, bv.w};
#pragma unroll
        for (int i = 0; i < 4; i++)
#pragma unroll
            for (int j = 0; j < 4; j++)
                acc[i][j] = fmaf(a[i], b[j], acc[i][j]);
    }

#pragma unroll
    for (int i = 0; i < 4; i++) {
        int b = ty * 4 + i;
        long bh = (long)b * H_ + h;
#pragma unroll
        for (int j = 0; j < 4; j += 2) {
            int n = n0 + tx * 4 + j;
            float x0 = acc[i][j], x1 = acc[i][j + 1];
            *(float2*)(T + bh * E_ + n) = make_float2(x0, x1);
            st_hilo_pair(Text + bh * KE + n, x0, x1);
        }
    }
}

// ====== fused scores + softmax + US-ext (per-bh; TK from 2 partials) =======
__global__ void __launch_bounds__(128) scores_us_kernel(
    const float* __restrict__ partTK, const float* __restrict__ T,
    const float* __restrict__ partq, const float* __restrict__ sampled,
    const float* __restrict__ in_proj_b, const float* __restrict__ bs,
    __nv_bfloat16* __restrict__ ext)
{
    int bh = blockIdx.x;
    int b = bh / H_, h = bh % H_;
    __shared__ float tk[E_];
    __shared__ float sc[NB];
    __shared__ float red[4];
    __shared__ float cbs;
    int tid = threadIdx.x;
    int w = tid >> 5, lane = tid & 31;
    const long spl = (long)B_ * E_;
    const long splTK = (long)BH * E_;

    const float* TKrow  = partTK + (long)bh * E_;
    const float* TKrow2 = partTK + splTK + (long)bh * E_;
    const float* Trow   = T + (long)bh * E_;
    float part = 0.f;
    for (int f = tid; f < E_; f += 128) {
        float t = TKrow[f] + TKrow2[f];
        tk[f] = t;
        part += Trow[f] * bs[f];
    }
    if (tid < HD) {
        long qo = (long)b * E_ + h * HD + tid;
        float qv = partq[qo] + partq[spl + qo] + partq[2 * spl + qo] + partq[3 * spl + qo]
                 + in_proj_b[h * HD + tid];
        part += qv * in_proj_b[E_ + h * HD + tid];
    }
#pragma unroll
    for (int o = 16; o; o >>= 1) part += __shfl_xor_sync(0xffffffffu, part, o);
    if (lane == 0) red[w] = part;
    __syncthreads();
    if (tid == 0) cbs = red[0] + red[1] + red[2] + red[3];
    __syncthreads();

    float cb = cbs;
#pragma unroll
    for (int pi = 0; pi < 8; pi++) {
        int p = w * 8 + pi;
        const float* srow = sampled + ((long)b * NB + p) * E_;
        float d = 0.f;
        for (int f = lane; f < E_; f += 32) d = fmaf(tk[f], srow[f], d);
#pragma unroll
        for (int o = 16; o; o >>= 1) d += __shfl_xor_sync(0xffffffffu, d, o);
        if (lane == 0) sc[p] = (d + cb) * 0.125f;
    }
    __syncthreads();
    if (tid < NB) {
        float s = sc[tid];
        float m = s;
#pragma unroll
        for (int o = 16; o; o >>= 1) m = fmaxf(m, __shfl_xor_sync(0xffffffffu, m, o));
        float e = expf(s - m);
        float sum = e;
#pragma unroll
        for (int o = 16; o; o >>= 1) sum += __shfl_xor_sync(0xffffffffu, sum, o);
        sc[tid] = e / sum;
    }
    __syncthreads();

    const float4* S = reinterpret_cast<const float4*>(sampled) + (long)b * NB * E4;
    for (int f = tid; f < E4; f += 128) {
        float4 acc = make_float4(0.f, 0.f, 0.f, 0.f);
#pragma unroll 8
        for (int p = 0; p < NB; p++) {
            float wv = sc[p];
            float4 s = S[p * E4 + f];
            acc.x = fmaf(wv, s.x, acc.x); acc.y = fmaf(wv, s.y, acc.y);
            acc.z = fmaf(wv, s.z, acc.z); acc.w = fmaf(wv, s.w, acc.w);
        }
        __nv_bfloat16* e = ext + (long)bh * KE + 4 * f;
        st_hilo_pair(e, acc.x, acc.y);
        st_hilo_pair(e + 2, acc.z, acc.w);
    }
}

// ====== broadcast out: fused ao split-K reduce + bias + confidence =========
#define ONS 16
__global__ void __launch_bounds__(192) out_kernel(
    const float* __restrict__ part, const float* __restrict__ bo,
    const float* __restrict__ conf, float4* __restrict__ out)
{
    const int b = blockIdx.y, t = threadIdx.x;
    const long spl = (long)B_ * E_;
    long o = (long)b * E_ + 4 * t;
    float4 s = *(const float4*)(part + o);
#pragma unroll
    for (int sp = 1; sp < 4; sp++) {
        float4 v = *(const float4*)(part + sp * spl + o);
        s.x += v.x; s.y += v.y; s.z += v.z; s.w += v.w;
    }
    float4 bb = *(const float4*)(bo + 4 * t);
    float cf = conf[b];
    s.x = (s.x + bb.x) * cf; s.y = (s.y + bb.y) * cf;
    s.z = (s.z + bb.z) * cf; s.w = (s.w + bb.w) * cf;

    const int nlo = blockIdx.x * 33;
    const int nhi = min(nlo + 33, FULLN);
    float4* dst = out + (long)b * FULLN * E4 + t;
    for (int n = nlo; n < nhi; n++)
        dst[(long)n * E4] = s;
}

// ================================================================
extern "C" void kernel_launch(void* const* d_in, const int* in_sizes, int n_in,
                              void* d_out, int out_size)
{
    const float* x    = (const float*)d_in[0];
    const float* bio  = (const float*)d_in[1];
    const float* base = (const float*)d_in[2];
    const float* off  = (const float*)d_in[3];
    const float* conf = (const float*)d_in[4];
    const float* Ws   = (const float*)d_in[5];
    const float* bs   = (const float*)d_in[6];
    const float* Win  = (const float*)d_in[7];
    const float* bin  = (const float*)d_in[8];
    const float* Wo   = (const float*)d_in[9];
    const float* bo   = (const float*)d_in[10];
    float* out = (float*)d_out;

    float *sampled, *T, *part, *partq, *partBig;
    cudaGetSymbolAddress((void**)&sampled, g_sampled);
    cudaGetSymbolAddress((void**)&T,       g_T);
    cudaGetSymbolAddress((void**)&part,    g_part);
    cudaGetSymbolAddress((void**)&partq,   g_partq);
    cudaGetSymbolAddress((void**)&partBig, g_partBig);

    __nv_bfloat16 *ext1, *Uext, *Wsext, *Wstext, *Wq, *Wv, *Wox, *bioext, *ctxext;
    cudaGetSymbolAddress((void**)&ext1,   g_ext1);
    cudaGetSymbolAddress((void**)&Uext,   g_Uext);
    cudaGetSymbolAddress((void**)&Wsext,  g_Wsext);
    cudaGetSymbolAddress((void**)&Wstext, g_Wstext);
    cudaGetSymbolAddress((void**)&Wq,     g_Wq);
    cudaGetSymbolAddress((void**)&Wv,     g_Wv);
    cudaGetSymbolAddress((void**)&Wox,    g_Wo);
    cudaGetSymbolAddress((void**)&bioext, g_bioext);
    cudaGetSymbolAddress((void**)&ctxext, g_ctxext);

    cudaFuncSetAttribute(hmma_kernel,
                         cudaFuncAttributeMaxDynamicSharedMemorySize, SMEM2);

    const long spl    = (long)B_ * E_;
    const long splBig = (long)BH * E_;

    // 1) merged: all conversions + trilinear sample (one launch)
    prep_sample_kernel<<<MERGED_BLOCKS, 256>>>(
        Ws, Win, Wo, bio, Wsext, Wstext, Wq, Wv, Wox, bioext,
        x, base, off, sampled);

    // 2) q partials = bio @ Wq.T  (split-K=4; reduce fused into consumers)
    hmma_kernel<<<dim3(12, 1, 4), 128, SMEM2>>>(
        bioext, KE, 0, Wq, 0, nullptr, partq, nullptr, 0, 4, KE, spl);

    // 3) T_h = q_h @ Wk_h  (q reduced inline) -> T fp32 + T ext
    qk_head_kernel<<<dim3(12, H_), 256>>>(partq, bin, Win + E_ * E_, T, ext1);

    // 4) TK partials = T @ Ws  (split-K=2; reduce fused into scores_us)
    hmma_kernel<<<dim3(12, 12, 2), 128, SMEM2>>>(
        ext1, KE, 0, Wstext, 0, nullptr, partBig, nullptr, 0, 2, KE, splBig);

    // 5) scores + softmax + US-ext (fused, per-bh; sums TK partials inline)
    scores_us_kernel<<<BH, 128>>>(partBig, T, partq, sampled, bin, bs, ext1);

    // 6) U = US @ Ws.T + bs  (big HMMA, nSplit=1) -> U ext
    hmma_kernel<<<dim3(12, 12, 1), 128, SMEM2>>>(
        ext1, KE, 0, Wsext, 0, bs, nullptr, Uext, 0, 1, KE, 0);

    // 7) ctx_h = U_h @ Wv_h.T  (per-head, split-K=4) + reduce -> ctx ext
    hmma_kernel<<<dim3(1, 1, H_ * 4), 128, SMEM2>>>(
        Uext, (long)H_ * KE, KE, Wv, (long)HD * KE,
        nullptr, part, nullptr, HD, 4, KE, spl);
    reduce2_kernel<<<48, 256>>>(part, bin + 2 * E_, nullptr, ctxext, 4);

    // 8) ao partials = ctx @ Wo.T  (split-K=4; reduce fused into out)
    hmma_kernel<<<dim3(12, 1, 4), 128, SMEM2>>>(
        ctxext, KE, 0, Wox, 0, nullptr, part, nullptr, 0, 4, KE, spl);

    // 9) out = (reduce(ao) + bo) * confidence, broadcast over N
    out_kernel<<<dim3(ONS, B_), 192>>>(part, bo, conf, (float4*)out);
}